// round 11
// baseline (speedup 1.0000x reference)
#include <cuda_runtime.h>
#include <cuda_fp16.h>

typedef unsigned int u32;
typedef unsigned long long u64;

#define NE   8
#define DD   512
#define DFF  2048
#define NTOK 4096

// ---------------- device scratch (no allocation allowed) ----------------
__device__ __half g_x  [(size_t)NTOK*DD];
__device__ __half g_w1 [(size_t)NE*DFF*DD];     // W1^T per expert [2048,512]
__device__ __half g_w2 [(size_t)NE*DD*DFF];     // W2^T per expert [512,2048]
__device__ __half g_wq [DD*DD];
__device__ __half g_wkv[2*DD*DD];               // [Wk;Wv] rows concat -> [1024,512]
__device__ __half g_wo [DD*DD];
__device__ float  g_bkv[2*DD];
__device__ __half g_hid[(size_t)NE*NTOK*DFF];
__device__ __half g_eo [(size_t)NE*NTOK*DD];
__device__ __half g_kv [(size_t)NE*NTOK*2*DD];  // fp16: [e][tok][0:512]=k, [512:1024]=v
__device__ float  g_q  [(size_t)NTOK*DD];
__device__ __half g_cx [(size_t)NTOK*DD];

// ---------------- helpers ----------------
__device__ __forceinline__ u32 smem_u32(const void* p) {
    return (u32)__cvta_generic_to_shared(p);
}
__device__ __forceinline__ void cpa16(u32 dst, const void* src) {
    asm volatile("cp.async.cg.shared.global [%0], [%1], 16;" :: "r"(dst), "l"(src));
}
#define CPA_COMMIT() asm volatile("cp.async.commit_group;" ::: "memory")
#define CPA_WAIT1()  asm volatile("cp.async.wait_group 1;" ::: "memory")

__device__ __forceinline__ void ldsm_x4(u32* r, u32 addr) {
    asm volatile("ldmatrix.sync.aligned.m8n8.x4.shared.b16 {%0,%1,%2,%3}, [%4];"
                 : "=r"(r[0]), "=r"(r[1]), "=r"(r[2]), "=r"(r[3]) : "r"(addr));
}
__device__ __forceinline__ void ldsm_x2(u32* r, u32 addr) {
    asm volatile("ldmatrix.sync.aligned.m8n8.x2.shared.b16 {%0,%1}, [%2];"
                 : "=r"(r[0]), "=r"(r[1]) : "r"(addr));
}
__device__ __forceinline__ void mma16816(float* c, const u32* a, const u32* b) {
    asm volatile(
        "mma.sync.aligned.m16n8k16.row.col.f32.f16.f16.f32 "
        "{%0,%1,%2,%3}, {%4,%5,%6,%7}, {%8,%9}, {%0,%1,%2,%3};"
        : "+f"(c[0]), "+f"(c[1]), "+f"(c[2]), "+f"(c[3])
        : "r"(a[0]), "r"(a[1]), "r"(a[2]), "r"(a[3]), "r"(b[0]), "r"(b[1]));
}

// smem geometry: tile 128x128, ktile 32 (64B/row + 16 pad = 80B rows), slabs A,B
#define KTILE   32
#define ROWB    80
#define OFF_A   0
#define OFF_B   (128*ROWB)           // 10240
#define STAGEB  (2*128*ROWB)         // 20480
#define NSTAGE  3
#define SMEM_BYTES (NSTAGE * STAGEB) // 61440 -> 2 CTAs/SM (122880 <= 227KB)

// ---------------- fp16 mma.sync GEMM ----------------
// Geometry identical to the proven round-7 config (128x128, 8 warps, warp 64x32).
// Pipeline upgraded: 3 stages, ONE sync per k-tile, loads issued BEFORE compute
// so tile i+2 has 2 full compute periods in flight.
// Loop invariant at iter i top: groups {i, i+1} outstanding. WAIT1 retires i;
// sync publishes tile i to all threads AND guarantees everyone finished reading
// slot (i+2)%3 (= slot (i-1)%3) in compute i-1, so it is safe to overwrite.
template<int OUTMODE, bool RELU>
__global__ void __launch_bounds__(256, 2) mma_gemm(
    const __half* __restrict__ A, const __half* __restrict__ B,
    const float* __restrict__ biasg,
    float* __restrict__ Cf, __half* __restrict__ Ch,
    int N, int K,
    size_t sA, size_t sB, size_t sBias, size_t sC,
    const int* __restrict__ eidPtr, size_t eidStride)
{
    extern __shared__ __align__(128) char sm[];
    const int tid  = threadIdx.x;
    const int lane = tid & 31;
    const int wid  = tid >> 5;
    const int e    = blockIdx.z;
    const int m0   = blockIdx.y * 128;
    const int n0   = blockIdx.x * 128;

    size_t aoff = (size_t)e * sA;
    if (eidPtr) aoff += (size_t)(*eidPtr) * eidStride;
    const __half* pA = A + aoff;
    const __half* pB = B + (size_t)e * sB;
    const float* bias = biasg + (size_t)e * sBias;

    const u32 smb = smem_u32(sm);

    // ---- loader mapping: 128 rows x 64B/slab, 2 threads/row, 2x16B per slab ----
    const int lr = tid >> 1;
    const int lc = (tid & 1) * 2;
    const __half* gA = pA + (size_t)(m0 + lr) * K + lc * 8;
    const __half* gB = pB + (size_t)(n0 + lr) * K + lc * 8;
    const u32 so = (u32)(lr * ROWB + lc * 16);

    // ---- warp/compute mapping: warps 2x4, warp tile 64x32 ----
    const int wm = wid >> 2;
    const int wn = wid & 3;

    u32 offA[4][2], offB[4][2];
    {
        const int rA = wm * 64 + (lane & 15);
        const int cA = lane >> 4;
        #pragma unroll
        for (int im = 0; im < 4; im++)
            #pragma unroll
            for (int ks = 0; ks < 2; ks++)
                offA[im][ks] = (u32)((rA + im * 16) * ROWB + (ks * 2 + cA) * 16);
        const int rB = wn * 32 + (lane & 7);
        const int cB = (lane >> 3) & 1;
        #pragma unroll
        for (int in = 0; in < 4; in++)
            #pragma unroll
            for (int ks = 0; ks < 2; ks++)
                offB[in][ks] = (u32)((rB + in * 8) * ROWB + (ks * 2 + cB) * 16);
    }

    float acc[4][4][4];
    #pragma unroll
    for (int im = 0; im < 4; im++)
        #pragma unroll
        for (int in = 0; in < 4; in++)
            #pragma unroll
            for (int q = 0; q < 4; q++) acc[im][in][q] = 0.f;

    const int nt = K >> 5;

    // ---- prologue: stages 0,1 ----
    #pragma unroll
    for (int p = 0; p < 2; p++) {
        const int k0 = p * KTILE;
        const u32 b = smb + p * STAGEB;
        cpa16(b + OFF_A + so,      gA + k0);
        cpa16(b + OFF_A + so + 16, gA + k0 + 8);
        cpa16(b + OFF_B + so,      gB + k0);
        cpa16(b + OFF_B + so + 16, gB + k0 + 8);
        CPA_COMMIT();
    }

    int cslot = 0, wslot = 2;
    for (int i = 0; i < nt; i++) {
        CPA_WAIT1();          // retire group i -> own copies of tile i complete
        __syncthreads();      // publish tile i; everyone done reading slot wslot

        const int inext = i + 2;
        if (inext < nt) {     // issue tile i+2 BEFORE compute: 2 periods of flight
            const int k0 = inext * KTILE;
            const u32 b = smb + (u32)wslot * STAGEB;
            cpa16(b + OFF_A + so,      gA + k0);
            cpa16(b + OFF_A + so + 16, gA + k0 + 8);
            cpa16(b + OFF_B + so,      gB + k0);
            cpa16(b + OFF_B + so + 16, gB + k0 + 8);
        }
        CPA_COMMIT();

        const u32 stage = smb + (u32)cslot * STAGEB;
        #pragma unroll
        for (int ks = 0; ks < 2; ks++) {
            u32 a[4][4];
            #pragma unroll
            for (int im = 0; im < 4; im++)
                ldsm_x4(a[im], stage + OFF_A + offA[im][ks]);
            u32 b[4][2];
            #pragma unroll
            for (int in = 0; in < 4; in++)
                ldsm_x2(b[in], stage + OFF_B + offB[in][ks]);
            #pragma unroll
            for (int im = 0; im < 4; im++)
                #pragma unroll
                for (int in = 0; in < 4; in++)
                    mma16816(acc[im][in], a[im], b[in]);
        }
        cslot = (cslot == 2) ? 0 : cslot + 1;
        wslot = (wslot == 2) ? 0 : wslot + 1;
    }

    // ---- epilogue ----
    const int g = lane >> 2;
    const int cb_in = (lane & 3) * 2;
    #pragma unroll
    for (int in = 0; in < 4; in++) {
        const int col = n0 + wn * 32 + in * 8 + cb_in;
        const float bx = bias[col], by = bias[col + 1];
        #pragma unroll
        for (int im = 0; im < 4; im++) {
            const int r0 = m0 + wm * 64 + im * 16 + g;
            const int r1 = r0 + 8;
            float v00 = acc[im][in][0] + bx, v01 = acc[im][in][1] + by;
            float v10 = acc[im][in][2] + bx, v11 = acc[im][in][3] + by;
            if (RELU) {
                v00 = fmaxf(v00, 0.f); v01 = fmaxf(v01, 0.f);
                v10 = fmaxf(v10, 0.f); v11 = fmaxf(v11, 0.f);
            }
            if (OUTMODE == 0) {
                float* o = Cf + (size_t)e * sC;
                float2 a0 = {v00, v01}, a1 = {v10, v11};
                *(float2*)(o + (size_t)r0 * N + col) = a0;
                *(float2*)(o + (size_t)r1 * N + col) = a1;
            } else {
                __half* oh = Ch + (size_t)e * sC;
                __half2 p;
                p.x = __float2half_rn(v00); p.y = __float2half_rn(v01);
                *(__half2*)(oh + (size_t)r0 * N + col) = p;
                p.x = __float2half_rn(v10); p.y = __float2half_rn(v11);
                *(__half2*)(oh + (size_t)r1 * N + col) = p;
            }
        }
    }
}

// ---------------- conversion kernels ----------------
__global__ void k_half(const float* __restrict__ in, __half* __restrict__ out, int n4)
{
    const int i = blockIdx.x * 256 + threadIdx.x;
    if (i >= n4) return;
    const float4 u = ((const float4*)in)[i];
    __half h[4];
    h[0] = __float2half_rn(u.x); h[1] = __float2half_rn(u.y);
    h[2] = __float2half_rn(u.z); h[3] = __float2half_rn(u.w);
    ((uint2*)out)[i] = *(const uint2*)h;
}

// merged: Wk,Wv,Wq,Wo fp32->fp16 + bias concat, one launch (grid.y selects)
__global__ void k_half_w(const float* __restrict__ Wk, const float* __restrict__ Wv,
                         const float* __restrict__ Wq, const float* __restrict__ Wo,
                         const float* __restrict__ bk, const float* __restrict__ bv,
                         __half* __restrict__ wkv, __half* __restrict__ wq,
                         __half* __restrict__ wo, float* __restrict__ bkv)
{
    const int y = blockIdx.y;
    const int i = blockIdx.x * 256 + threadIdx.x;
    if (y == 4) {
        if (i < DD) bkv[i] = bk[i];
        else if (i < 2 * DD) bkv[i] = bv[i - DD];
        return;
    }
    const int n4 = DD * DD / 4;
    if (i >= n4) return;
    const float* src = (y == 0) ? Wk : (y == 1) ? Wv : (y == 2) ? Wq : Wo;
    __half* dst = (y == 0) ? wkv : (y == 1) ? (wkv + DD * DD) : (y == 2) ? wq : wo;
    const float4 u = ((const float4*)src)[i];
    __half h[4];
    h[0] = __float2half_rn(u.x); h[1] = __float2half_rn(u.y);
    h[2] = __float2half_rn(u.z); h[3] = __float2half_rn(u.w);
    ((uint2*)dst)[i] = *(const uint2*)h;
}

// transpose + convert: in [R,C] fp32 (batched over z) -> out [C,R] fp16
__global__ void k_thalf(const float* __restrict__ in, __half* __restrict__ out,
                        int R, int C)
{
    __shared__ float t[32][33];
    const size_t zo = (size_t)blockIdx.z * R * C;
    const int c0 = blockIdx.x * 32, r0 = blockIdx.y * 32;
    const int tx = threadIdx.x, ty = threadIdx.y;
    #pragma unroll
    for (int rr = ty; rr < 32; rr += 8)
        t[rr][tx] = in[zo + (size_t)(r0 + rr) * C + c0 + tx];
    __syncthreads();
    #pragma unroll
    for (int cc = ty; cc < 32; cc += 8)
        out[zo + (size_t)(c0 + cc) * R + r0 + tx] = __float2half_rn(t[tx][cc]);
}

// ---------------- attention over the expert axis (E=8), fp16 kv ----------------
__global__ void attn_kernel(const float* __restrict__ q,
                            const __half* __restrict__ kvbuf,
                            __half* __restrict__ ctx,
                            const int* __restrict__ eidPtr)
{
    const int n    = blockIdx.x;
    const int head = threadIdx.x >> 5;
    const int lane = threadIdx.x & 31;
    const int eid  = *eidPtr;

    const int hb   = head * 64 + 2 * lane;
    const float2 qv = *(const float2*)(q + n * DD + hb);
    const __half* kvn = kvbuf + (size_t)n * 2 * DD;

    float s[NE];
    #pragma unroll
    for (int f = 0; f < NE; f++) {
        const __half2 kh = *(const __half2*)(kvn + (size_t)f * NTOK * 2 * DD + hb);
        const float2 kv = __half22float2(kh);
        float p = qv.x * kv.x + qv.y * kv.y;
        #pragma unroll
        for (int off = 16; off > 0; off >>= 1)
            p += __shfl_xor_sync(0xffffffffu, p, off);
        s[f] = p * 0.125f + ((f <= eid) ? 1.0f : 0.0f);
    }

    float mx = s[0];
    #pragma unroll
    for (int f = 1; f < NE; f++) mx = fmaxf(mx, s[f]);
    float sum = 0.f;
    #pragma unroll
    for (int f = 0; f < NE; f++) { s[f] = expf(s[f] - mx); sum += s[f]; }
    const float inv = 1.f / sum;

    float cx = 0.f, cy = 0.f;
    #pragma unroll
    for (int f = 0; f < NE; f++) {
        const __half2 vh = *(const __half2*)(kvn + (size_t)f * NTOK * 2 * DD + DD + hb);
        const float2 vv = __half22float2(vh);
        const float p = s[f] * inv;
        cx += p * vv.x; cy += p * vv.y;
    }
    __half2 o;
    o.x = __float2half_rn(cx); o.y = __float2half_rn(cy);
    *(__half2*)(ctx + n * DD + hb) = o;
}

// -----------------------------------------------------------------------------
extern "C" void kernel_launch(void* const* d_in, const int* in_sizes, int n_in,
                              void* d_out, int out_size)
{
    const float* x  = (const float*)d_in[0];
    const float* W1 = (const float*)d_in[1];
    const float* b1 = (const float*)d_in[2];
    const float* W2 = (const float*)d_in[3];
    const float* b2 = (const float*)d_in[4];
    const float* Wq = (const float*)d_in[5];
    const float* bq = (const float*)d_in[6];
    const float* Wk = (const float*)d_in[7];
    const float* bk = (const float*)d_in[8];
    const float* Wv = (const float*)d_in[9];
    const float* bv = (const float*)d_in[10];
    const float* Wo = (const float*)d_in[11];
    const float* bo = (const float*)d_in[12];
    const int*  eid = (const int*)  d_in[13];

    __half *xh, *w1, *w2, *wq, *wkv, *wo, *hid, *eo, *cx, *kvb;
    float *qb, *bkv;
    cudaGetSymbolAddress((void**)&xh,  g_x);
    cudaGetSymbolAddress((void**)&w1,  g_w1);
    cudaGetSymbolAddress((void**)&w2,  g_w2);
    cudaGetSymbolAddress((void**)&wq,  g_wq);
    cudaGetSymbolAddress((void**)&wkv, g_wkv);
    cudaGetSymbolAddress((void**)&wo,  g_wo);
    cudaGetSymbolAddress((void**)&hid, g_hid);
    cudaGetSymbolAddress((void**)&eo,  g_eo);
    cudaGetSymbolAddress((void**)&cx,  g_cx);
    cudaGetSymbolAddress((void**)&kvb, g_kv);
    cudaGetSymbolAddress((void**)&qb,  g_q);
    cudaGetSymbolAddress((void**)&bkv, g_bkv);

    cudaFuncSetAttribute(mma_gemm<0, false>, cudaFuncAttributeMaxDynamicSharedMemorySize, SMEM_BYTES);
    cudaFuncSetAttribute(mma_gemm<1, false>, cudaFuncAttributeMaxDynamicSharedMemorySize, SMEM_BYTES);
    cudaFuncSetAttribute(mma_gemm<1, true>,  cudaFuncAttributeMaxDynamicSharedMemorySize, SMEM_BYTES);

    // ---- launches 1-4: conversions; 5/6 are FFN1/FFN2 (ncu -s 5 -c 1 target) ----
    k_half<<<(NTOK * DD / 4 + 255) / 256, 256>>>(x, xh, NTOK * DD / 4);             // 1
    {   // 2: W1 [E,512,2048] -> [E,2048,512]
        dim3 g(DFF / 32, DD / 32, NE), b(32, 8);
        k_thalf<<<g, b>>>(W1, w1, DD, DFF);
    }
    {   // 3: W2 [E,2048,512] -> [E,512,2048]
        dim3 g(DD / 32, DFF / 32, NE), b(32, 8);
        k_thalf<<<g, b>>>(W2, w2, DFF, DD);
    }
    {   // 4: all projection weights + bias concat in one launch
        dim3 g(DD * DD / 4 / 256, 5);
        k_half_w<<<g, 256>>>(Wk, Wv, Wq, Wo, bk, bv, wkv, wq, wo, bkv);
    }

    // ---- 5: FFN1: hidden[e] = relu(x @ W1[e] + b1[e])  M=4096, N=2048, K=512 ----
    mma_gemm<1, true><<<dim3(DFF / 128, NTOK / 128, NE), 256, SMEM_BYTES>>>(
        xh, w1, b1, nullptr, hid,
        DFF, DD, 0, (size_t)DFF * DD, DFF, (size_t)NTOK * DFF, nullptr, 0);

    // ---- 6: FFN2: eo[e] = hidden[e] @ W2[e] + b2[e]  N=512, K=2048 ----
    mma_gemm<1, false><<<dim3(DD / 128, NTOK / 128, NE), 256, SMEM_BYTES>>>(
        hid, w2, b2, nullptr, eo,
        DD, DFF, (size_t)NTOK * DFF, (size_t)DD * DFF, DD, (size_t)NTOK * DD, nullptr, 0);

    // ---- KV proj (fused, fp16 out): kv[e] = eo[e] @ [Wk;Wv]^T + [bk;bv] ----
    mma_gemm<1, false><<<dim3(2 * DD / 128, NTOK / 128, NE), 256, SMEM_BYTES>>>(
        eo, wkv, bkv, nullptr, kvb,
        2 * DD, DD, (size_t)NTOK * DD, 0, 0, (size_t)NTOK * 2 * DD, nullptr, 0);

    // ---- Q proj (expert_id slice only, fp32 out) ----
    mma_gemm<0, false><<<dim3(DD / 128, NTOK / 128, 1), 256, SMEM_BYTES>>>(
        eo, wq, bq, qb, nullptr,
        DD, DD, 0, 0, 0, 0, eid, (size_t)NTOK * DD);

    // ---- attention over experts ----
    attn_kernel<<<NTOK, 256>>>(qb, kvb, cx, eid);

    // ---- out proj: d_out = ctx @ Wo^T + bo ----
    mma_gemm<0, false><<<dim3(DD / 128, NTOK / 128, 1), 256, SMEM_BYTES>>>(
        cx, wo, bo, (float*)d_out, nullptr,
        DD, DD, 0, 0, 0, 0, nullptr, 0);
}

// round 12
// speedup vs baseline: 1.0557x; 1.0557x over previous
#include <cuda_runtime.h>
#include <cuda_fp16.h>

typedef unsigned int u32;
typedef unsigned long long u64;

#define NE   8
#define DD   512
#define DFF  2048
#define NTOK 4096

// ---------------- device scratch (no allocation allowed) ----------------
__device__ __half g_x  [(size_t)NTOK*DD];
__device__ __half g_w1 [(size_t)NE*DFF*DD];     // W1^T per expert [2048,512]
__device__ __half g_w2 [(size_t)NE*DD*DFF];     // W2^T per expert [512,2048]
__device__ __half g_wq [DD*DD];
__device__ __half g_wkv[2*DD*DD];               // [Wk;Wv] rows concat -> [1024,512]
__device__ __half g_wo [DD*DD];
__device__ float  g_bkv[2*DD];
__device__ __half g_hid[(size_t)NE*NTOK*DFF];
__device__ __half g_eo [(size_t)NE*NTOK*DD];
__device__ __half g_kv [(size_t)NE*NTOK*2*DD];  // fp16: [e][tok][0:512]=k, [512:1024]=v
__device__ __half g_q  [(size_t)NTOK*DD];       // fp16 q (expert_id slice)
__device__ __half g_cx [(size_t)NTOK*DD];

// ---------------- helpers ----------------
__device__ __forceinline__ u32 smem_u32(const void* p) {
    return (u32)__cvta_generic_to_shared(p);
}
__device__ __forceinline__ void cpa16(u32 dst, const void* src) {
    asm volatile("cp.async.cg.shared.global [%0], [%1], 16;" :: "r"(dst), "l"(src));
}
#define CPA_COMMIT() asm volatile("cp.async.commit_group;" ::: "memory")
#define CPA_WAIT1()  asm volatile("cp.async.wait_group 1;" ::: "memory")

__device__ __forceinline__ void ldsm_x4(u32* r, u32 addr) {
    asm volatile("ldmatrix.sync.aligned.m8n8.x4.shared.b16 {%0,%1,%2,%3}, [%4];"
                 : "=r"(r[0]), "=r"(r[1]), "=r"(r[2]), "=r"(r[3]) : "r"(addr));
}
__device__ __forceinline__ void mma16816(float* c, const u32* a, const u32* b) {
    asm volatile(
        "mma.sync.aligned.m16n8k16.row.col.f32.f16.f16.f32 "
        "{%0,%1,%2,%3}, {%4,%5,%6,%7}, {%8,%9}, {%0,%1,%2,%3};"
        : "+f"(c[0]), "+f"(c[1]), "+f"(c[2]), "+f"(c[3])
        : "r"(a[0]), "r"(a[1]), "r"(a[2]), "r"(a[3]), "r"(b[0]), "r"(b[1]));
}

// smem geometry: tile 128x128, ktile 32 (64B/row + 16 pad = 80B rows), slabs A,B
#define KTILE   32
#define ROWB    80
#define OFF_A   0
#define OFF_B   (128*ROWB)           // 10240
#define STAGEB  (2*128*ROWB)         // 20480
#define NSTAGE  3
#define SMEM_BYTES (NSTAGE * STAGEB) // 61440 -> 2 CTAs/SM

// ---------------- fp16 mma.sync GEMM ----------------
// Proven geometry: 128x128 tile, 8 warps (2x4), warp tile 64x32, 2 CTAs/SM.
// 3-stage pipeline, one sync per k-tile, loads issued before compute.
// B fragments loaded pairwise with ldsm_x4 (two n-tiles per instruction).
template<int OUTMODE, bool RELU>
__global__ void __launch_bounds__(256, 2) mma_gemm(
    const __half* __restrict__ A, const __half* __restrict__ B,
    const float* __restrict__ biasg,
    float* __restrict__ Cf, __half* __restrict__ Ch,
    int N, int K,
    size_t sA, size_t sB, size_t sBias, size_t sC,
    const int* __restrict__ eidPtr, size_t eidStride)
{
    extern __shared__ __align__(128) char sm[];
    const int tid  = threadIdx.x;
    const int lane = tid & 31;
    const int wid  = tid >> 5;
    const int e    = blockIdx.z;
    const int m0   = blockIdx.y * 128;
    const int n0   = blockIdx.x * 128;

    size_t aoff = (size_t)e * sA;
    if (eidPtr) aoff += (size_t)(*eidPtr) * eidStride;
    const __half* pA = A + aoff;
    const __half* pB = B + (size_t)e * sB;
    const float* bias = biasg + (size_t)e * sBias;

    const u32 smb = smem_u32(sm);

    // ---- loader mapping: 128 rows x 64B/slab, 2 threads/row, 2x16B per slab ----
    const int lr = tid >> 1;
    const int lc = (tid & 1) * 2;
    const __half* gA = pA + (size_t)(m0 + lr) * K + lc * 8;
    const __half* gB = pB + (size_t)(n0 + lr) * K + lc * 8;
    const u32 so = (u32)(lr * ROWB + lc * 16);

    // ---- warp/compute mapping: warps 2x4, warp tile 64x32 ----
    const int wm = wid >> 2;
    const int wn = wid & 3;

    // A fragments: one m16 tile per ldsm_x4 (as before)
    u32 offA[4][2];
    {
        const int rA = wm * 64 + (lane & 15);
        const int cA = lane >> 4;
        #pragma unroll
        for (int im = 0; im < 4; im++)
            #pragma unroll
            for (int ks = 0; ks < 2; ks++)
                offA[im][ks] = (u32)((rA + im * 16) * ROWB + (ks * 2 + cA) * 16);
    }
    // B fragments: PAIR of n8 tiles per ldsm_x4.
    // matrices: (n-lo,k-lo16B),(n-lo,k-hi16B),(n-hi,k-lo),(n-hi,k-hi)
    // lane groups g=lane>>3: g0->m0, g1->m1, g2->m2, g3->m3.
    u32 offBP[2][2];
    {
        const int rB = wn * 32 + ((lane >> 4) & 1) * 8 + (lane & 7);
        const int cB = (lane >> 3) & 1;
        #pragma unroll
        for (int p = 0; p < 2; p++)
            #pragma unroll
            for (int ks = 0; ks < 2; ks++)
                offBP[p][ks] = (u32)((rB + p * 16) * ROWB + (ks * 2 + cB) * 16);
    }

    float acc[4][4][4];
    #pragma unroll
    for (int im = 0; im < 4; im++)
        #pragma unroll
        for (int in = 0; in < 4; in++)
            #pragma unroll
            for (int q = 0; q < 4; q++) acc[im][in][q] = 0.f;

    const int nt = K >> 5;

    // ---- prologue: stages 0,1 ----
    #pragma unroll
    for (int p = 0; p < 2; p++) {
        const int k0 = p * KTILE;
        const u32 b = smb + p * STAGEB;
        cpa16(b + OFF_A + so,      gA + k0);
        cpa16(b + OFF_A + so + 16, gA + k0 + 8);
        cpa16(b + OFF_B + so,      gB + k0);
        cpa16(b + OFF_B + so + 16, gB + k0 + 8);
        CPA_COMMIT();
    }

    int cslot = 0, wslot = 2;
    for (int i = 0; i < nt; i++) {
        CPA_WAIT1();
        __syncthreads();

        const int inext = i + 2;
        if (inext < nt) {
            const int k0 = inext * KTILE;
            const u32 b = smb + (u32)wslot * STAGEB;
            cpa16(b + OFF_A + so,      gA + k0);
            cpa16(b + OFF_A + so + 16, gA + k0 + 8);
            cpa16(b + OFF_B + so,      gB + k0);
            cpa16(b + OFF_B + so + 16, gB + k0 + 8);
        }
        CPA_COMMIT();

        const u32 stage = smb + (u32)cslot * STAGEB;
        #pragma unroll
        for (int ks = 0; ks < 2; ks++) {
            u32 a[4][4];
            #pragma unroll
            for (int im = 0; im < 4; im++)
                ldsm_x4(a[im], stage + OFF_A + offA[im][ks]);
            u32 b[2][4];   // b[p] = {frag(2p)[0], frag(2p)[1], frag(2p+1)[0], frag(2p+1)[1]}
            #pragma unroll
            for (int p = 0; p < 2; p++)
                ldsm_x4(b[p], stage + OFF_B + offBP[p][ks]);
            #pragma unroll
            for (int im = 0; im < 4; im++)
                #pragma unroll
                for (int in = 0; in < 4; in++)
                    mma16816(acc[im][in], a[im], b[in >> 1] + (in & 1) * 2);
        }
        cslot = (cslot == 2) ? 0 : cslot + 1;
        wslot = (wslot == 2) ? 0 : wslot + 1;
    }

    // ---- epilogue ----
    const int g = lane >> 2;
    const int cb_in = (lane & 3) * 2;
    #pragma unroll
    for (int in = 0; in < 4; in++) {
        const int col = n0 + wn * 32 + in * 8 + cb_in;
        const float bx = bias[col], by = bias[col + 1];
        #pragma unroll
        for (int im = 0; im < 4; im++) {
            const int r0 = m0 + wm * 64 + im * 16 + g;
            const int r1 = r0 + 8;
            float v00 = acc[im][in][0] + bx, v01 = acc[im][in][1] + by;
            float v10 = acc[im][in][2] + bx, v11 = acc[im][in][3] + by;
            if (RELU) {
                v00 = fmaxf(v00, 0.f); v01 = fmaxf(v01, 0.f);
                v10 = fmaxf(v10, 0.f); v11 = fmaxf(v11, 0.f);
            }
            if (OUTMODE == 0) {
                float* o = Cf + (size_t)e * sC;
                float2 a0 = {v00, v01}, a1 = {v10, v11};
                *(float2*)(o + (size_t)r0 * N + col) = a0;
                *(float2*)(o + (size_t)r1 * N + col) = a1;
            } else {
                __half* oh = Ch + (size_t)e * sC;
                __half2 p;
                p.x = __float2half_rn(v00); p.y = __float2half_rn(v01);
                *(__half2*)(oh + (size_t)r0 * N + col) = p;
                p.x = __float2half_rn(v10); p.y = __float2half_rn(v11);
                *(__half2*)(oh + (size_t)r1 * N + col) = p;
            }
        }
    }
}

// ---------------- conversion kernels ----------------
__global__ void k_half(const float* __restrict__ in, __half* __restrict__ out, int n4)
{
    const int i = blockIdx.x * 256 + threadIdx.x;
    if (i >= n4) return;
    const float4 u = ((const float4*)in)[i];
    __half h[4];
    h[0] = __float2half_rn(u.x); h[1] = __float2half_rn(u.y);
    h[2] = __float2half_rn(u.z); h[3] = __float2half_rn(u.w);
    ((uint2*)out)[i] = *(const uint2*)h;
}

// merged: Wk,Wv,Wq,Wo fp32->fp16 + bias concat, one launch (grid.y selects)
__global__ void k_half_w(const float* __restrict__ Wk, const float* __restrict__ Wv,
                         const float* __restrict__ Wq, const float* __restrict__ Wo,
                         const float* __restrict__ bk, const float* __restrict__ bv,
                         __half* __restrict__ wkv, __half* __restrict__ wq,
                         __half* __restrict__ wo, float* __restrict__ bkv)
{
    const int y = blockIdx.y;
    const int i = blockIdx.x * 256 + threadIdx.x;
    if (y == 4) {
        if (i < DD) bkv[i] = bk[i];
        else if (i < 2 * DD) bkv[i] = bv[i - DD];
        return;
    }
    const int n4 = DD * DD / 4;
    if (i >= n4) return;
    const float* src = (y == 0) ? Wk : (y == 1) ? Wv : (y == 2) ? Wq : Wo;
    __half* dst = (y == 0) ? wkv : (y == 1) ? (wkv + DD * DD) : (y == 2) ? wq : wo;
    const float4 u = ((const float4*)src)[i];
    __half h[4];
    h[0] = __float2half_rn(u.x); h[1] = __float2half_rn(u.y);
    h[2] = __float2half_rn(u.z); h[3] = __float2half_rn(u.w);
    ((uint2*)dst)[i] = *(const uint2*)h;
}

// transpose + convert: in [R,C] fp32 (batched over z) -> out [C,R] fp16
__global__ void k_thalf(const float* __restrict__ in, __half* __restrict__ out,
                        int R, int C)
{
    __shared__ float t[32][33];
    const size_t zo = (size_t)blockIdx.z * R * C;
    const int c0 = blockIdx.x * 32, r0 = blockIdx.y * 32;
    const int tx = threadIdx.x, ty = threadIdx.y;
    #pragma unroll
    for (int rr = ty; rr < 32; rr += 8)
        t[rr][tx] = in[zo + (size_t)(r0 + rr) * C + c0 + tx];
    __syncthreads();
    #pragma unroll
    for (int cc = ty; cc < 32; cc += 8)
        out[zo + (size_t)(c0 + cc) * R + r0 + tx] = __float2half_rn(t[tx][cc]);
}

// ---------------- attention over the expert axis (E=8), fp16 q/kv ----------------
__global__ void attn_kernel(const __half* __restrict__ q,
                            const __half* __restrict__ kvbuf,
                            __half* __restrict__ ctx,
                            const int* __restrict__ eidPtr)
{
    const int n    = blockIdx.x;
    const int head = threadIdx.x >> 5;
    const int lane = threadIdx.x & 31;
    const int eid  = *eidPtr;

    const int hb   = head * 64 + 2 * lane;
    const float2 qv = __half22float2(*(const __half2*)(q + n * DD + hb));
    const __half* kvn = kvbuf + (size_t)n * 2 * DD;

    float s[NE];
    #pragma unroll
    for (int f = 0; f < NE; f++) {
        const float2 kv = __half22float2(
            *(const __half2*)(kvn + (size_t)f * NTOK * 2 * DD + hb));
        float p = qv.x * kv.x + qv.y * kv.y;
        #pragma unroll
        for (int off = 16; off > 0; off >>= 1)
            p += __shfl_xor_sync(0xffffffffu, p, off);
        s[f] = p * 0.125f + ((f <= eid) ? 1.0f : 0.0f);
    }

    float mx = s[0];
    #pragma unroll
    for (int f = 1; f < NE; f++) mx = fmaxf(mx, s[f]);
    float sum = 0.f;
    #pragma unroll
    for (int f = 0; f < NE; f++) { s[f] = expf(s[f] - mx); sum += s[f]; }
    const float inv = 1.f / sum;

    float cx = 0.f, cy = 0.f;
    #pragma unroll
    for (int f = 0; f < NE; f++) {
        const float2 vv = __half22float2(
            *(const __half2*)(kvn + (size_t)f * NTOK * 2 * DD + DD + hb));
        const float p = s[f] * inv;
        cx += p * vv.x; cy += p * vv.y;
    }
    __half2 o;
    o.x = __float2half_rn(cx); o.y = __float2half_rn(cy);
    *(__half2*)(ctx + n * DD + hb) = o;
}

// -----------------------------------------------------------------------------
extern "C" void kernel_launch(void* const* d_in, const int* in_sizes, int n_in,
                              void* d_out, int out_size)
{
    const float* x  = (const float*)d_in[0];
    const float* W1 = (const float*)d_in[1];
    const float* b1 = (const float*)d_in[2];
    const float* W2 = (const float*)d_in[3];
    const float* b2 = (const float*)d_in[4];
    const float* Wq = (const float*)d_in[5];
    const float* bq = (const float*)d_in[6];
    const float* Wk = (const float*)d_in[7];
    const float* bk = (const float*)d_in[8];
    const float* Wv = (const float*)d_in[9];
    const float* bv = (const float*)d_in[10];
    const float* Wo = (const float*)d_in[11];
    const float* bo = (const float*)d_in[12];
    const int*  eid = (const int*)  d_in[13];

    __half *xh, *w1, *w2, *wq, *wkv, *wo, *hid, *eo, *cx, *kvb, *qb;
    float *bkv;
    cudaGetSymbolAddress((void**)&xh,  g_x);
    cudaGetSymbolAddress((void**)&w1,  g_w1);
    cudaGetSymbolAddress((void**)&w2,  g_w2);
    cudaGetSymbolAddress((void**)&wq,  g_wq);
    cudaGetSymbolAddress((void**)&wkv, g_wkv);
    cudaGetSymbolAddress((void**)&wo,  g_wo);
    cudaGetSymbolAddress((void**)&hid, g_hid);
    cudaGetSymbolAddress((void**)&eo,  g_eo);
    cudaGetSymbolAddress((void**)&cx,  g_cx);
    cudaGetSymbolAddress((void**)&kvb, g_kv);
    cudaGetSymbolAddress((void**)&qb,  g_q);
    cudaGetSymbolAddress((void**)&bkv, g_bkv);

    cudaFuncSetAttribute(mma_gemm<0, false>, cudaFuncAttributeMaxDynamicSharedMemorySize, SMEM_BYTES);
    cudaFuncSetAttribute(mma_gemm<1, false>, cudaFuncAttributeMaxDynamicSharedMemorySize, SMEM_BYTES);
    cudaFuncSetAttribute(mma_gemm<1, true>,  cudaFuncAttributeMaxDynamicSharedMemorySize, SMEM_BYTES);

    // ---- launches 1-4: conversions; 5/6 are FFN1/FFN2 (ncu -s 5 -c 1 target) ----
    k_half<<<(NTOK * DD / 4 + 255) / 256, 256>>>(x, xh, NTOK * DD / 4);             // 1
    {   // 2: W1 [E,512,2048] -> [E,2048,512]
        dim3 g(DFF / 32, DD / 32, NE), b(32, 8);
        k_thalf<<<g, b>>>(W1, w1, DD, DFF);
    }
    {   // 3: W2 [E,2048,512] -> [E,512,2048]
        dim3 g(DD / 32, DFF / 32, NE), b(32, 8);
        k_thalf<<<g, b>>>(W2, w2, DFF, DD);
    }
    {   // 4: all projection weights + bias concat in one launch
        dim3 g(DD * DD / 4 / 256, 5);
        k_half_w<<<g, 256>>>(Wk, Wv, Wq, Wo, bk, bv, wkv, wq, wo, bkv);
    }

    // ---- 5: FFN1: hidden[e] = relu(x @ W1[e] + b1[e])  M=4096, N=2048, K=512 ----
    mma_gemm<1, true><<<dim3(DFF / 128, NTOK / 128, NE), 256, SMEM_BYTES>>>(
        xh, w1, b1, nullptr, hid,
        DFF, DD, 0, (size_t)DFF * DD, DFF, (size_t)NTOK * DFF, nullptr, 0);

    // ---- 6: FFN2: eo[e] = hidden[e] @ W2[e] + b2[e]  N=512, K=2048 ----
    mma_gemm<1, false><<<dim3(DD / 128, NTOK / 128, NE), 256, SMEM_BYTES>>>(
        hid, w2, b2, nullptr, eo,
        DD, DFF, (size_t)NTOK * DFF, (size_t)DD * DFF, DD, (size_t)NTOK * DD, nullptr, 0);

    // ---- KV proj (fused, fp16 out): kv[e] = eo[e] @ [Wk;Wv]^T + [bk;bv] ----
    mma_gemm<1, false><<<dim3(2 * DD / 128, NTOK / 128, NE), 256, SMEM_BYTES>>>(
        eo, wkv, bkv, nullptr, kvb,
        2 * DD, DD, (size_t)NTOK * DD, 0, 0, (size_t)NTOK * 2 * DD, nullptr, 0);

    // ---- Q proj (expert_id slice only, fp16 out) ----
    mma_gemm<1, false><<<dim3(DD / 128, NTOK / 128, 1), 256, SMEM_BYTES>>>(
        eo, wq, bq, nullptr, qb,
        DD, DD, 0, 0, 0, 0, eid, (size_t)NTOK * DD);

    // ---- attention over experts ----
    attn_kernel<<<NTOK, 256>>>(qb, kvb, cx, eid);

    // ---- out proj: d_out = ctx @ Wo^T + bo ----
    mma_gemm<0, false><<<dim3(DD / 128, NTOK / 128, 1), 256, SMEM_BYTES>>>(
        cx, wo, bo, (float*)d_out, nullptr,
        DD, DD, 0, 0, 0, 0, nullptr, 0);
}

// round 13
// speedup vs baseline: 1.1109x; 1.0523x over previous
#include <cuda_runtime.h>
#include <cuda_fp16.h>

typedef unsigned int u32;
typedef unsigned long long u64;

#define NE   8
#define DD   512
#define DFF  2048
#define NTOK 4096

// ---------------- device scratch (no allocation allowed) ----------------
__device__ __half g_x  [(size_t)NTOK*DD];
__device__ __half g_w1 [(size_t)NE*DFF*DD];     // W1^T per expert [2048,512]
__device__ __half g_w2 [(size_t)NE*DD*DFF];     // W2^T per expert [512,2048]
__device__ __half g_wq [DD*DD];
__device__ __half g_wk [DD*DD];                 // Wk [512,512]
__device__ __half g_wo [DD*DD];
__device__ __half g_wvp[(size_t)NE*128*DD];     // Wv per head, padded to 128 rows
__device__ __half g_hid[(size_t)NE*NTOK*DFF];
__device__ __half g_eo [(size_t)NE*NTOK*DD];
__device__ __half g_k  [(size_t)NE*NTOK*DD];    // fp16 k per expert
__device__ __half g_m  [(size_t)NE*NTOK*DD];    // fp16 per-head mixed eo (h as batch)
__device__ __half g_q  [(size_t)NTOK*DD];       // fp16 q (expert_id slice)
__device__ __half g_cx [(size_t)NTOK*DD];

// ---------------- helpers ----------------
__device__ __forceinline__ u32 smem_u32(const void* p) {
    return (u32)__cvta_generic_to_shared(p);
}
__device__ __forceinline__ void cpa16(u32 dst, const void* src) {
    asm volatile("cp.async.cg.shared.global [%0], [%1], 16;" :: "r"(dst), "l"(src));
}
#define CPA_COMMIT() asm volatile("cp.async.commit_group;" ::: "memory")
#define CPA_WAIT1()  asm volatile("cp.async.wait_group 1;" ::: "memory")

__device__ __forceinline__ void ldsm_x4(u32* r, u32 addr) {
    asm volatile("ldmatrix.sync.aligned.m8n8.x4.shared.b16 {%0,%1,%2,%3}, [%4];"
                 : "=r"(r[0]), "=r"(r[1]), "=r"(r[2]), "=r"(r[3]) : "r"(addr));
}
__device__ __forceinline__ void mma16816(float* c, const u32* a, const u32* b) {
    asm volatile(
        "mma.sync.aligned.m16n8k16.row.col.f32.f16.f16.f32 "
        "{%0,%1,%2,%3}, {%4,%5,%6,%7}, {%8,%9}, {%0,%1,%2,%3};"
        : "+f"(c[0]), "+f"(c[1]), "+f"(c[2]), "+f"(c[3])
        : "r"(a[0]), "r"(a[1]), "r"(a[2]), "r"(a[3]), "r"(b[0]), "r"(b[1]));
}

// smem geometry: tile 128x128, ktile 32 (64B/row + 16 pad = 80B rows), slabs A,B
#define KTILE   32
#define ROWB    80
#define OFF_A   0
#define OFF_B   (128*ROWB)           // 10240
#define STAGEB  (2*128*ROWB)         // 20480
#define NSTAGE  3
#define SMEM_BYTES (NSTAGE * STAGEB) // 61440 -> 2 CTAs/SM

// ---------------- fp16 mma.sync GEMM (round-12 proven config) ----------------
// OUTMODE: 0 -> fp32 Cf; 1 -> fp16 Ch; 2 -> fp16 Ch, only cols 0..63 valid
// (warps wn>=2 skip epilogue; e*sC is a COLUMN offset, ld = N).
template<int OUTMODE, bool RELU>
__global__ void __launch_bounds__(256, 2) mma_gemm(
    const __half* __restrict__ A, const __half* __restrict__ B,
    const float* __restrict__ biasg,
    float* __restrict__ Cf, __half* __restrict__ Ch,
    int N, int K,
    size_t sA, size_t sB, size_t sBias, size_t sC,
    const int* __restrict__ eidPtr, size_t eidStride)
{
    extern __shared__ __align__(128) char sm[];
    const int tid  = threadIdx.x;
    const int lane = tid & 31;
    const int wid  = tid >> 5;
    const int e    = blockIdx.z;
    const int m0   = blockIdx.y * 128;
    const int n0   = blockIdx.x * 128;

    size_t aoff = (size_t)e * sA;
    if (eidPtr) aoff += (size_t)(*eidPtr) * eidStride;
    const __half* pA = A + aoff;
    const __half* pB = B + (size_t)e * sB;
    const float* bias = biasg + (size_t)e * sBias;

    const u32 smb = smem_u32(sm);

    // ---- loader mapping: 128 rows x 64B/slab, 2 threads/row, 2x16B per slab ----
    const int lr = tid >> 1;
    const int lc = (tid & 1) * 2;
    const __half* gA = pA + (size_t)(m0 + lr) * K + lc * 8;
    const __half* gB = pB + (size_t)(n0 + lr) * K + lc * 8;
    const u32 so = (u32)(lr * ROWB + lc * 16);

    // ---- warp/compute mapping: warps 2x4, warp tile 64x32 ----
    const int wm = wid >> 2;
    const int wn = wid & 3;

    u32 offA[4][2];
    {
        const int rA = wm * 64 + (lane & 15);
        const int cA = lane >> 4;
        #pragma unroll
        for (int im = 0; im < 4; im++)
            #pragma unroll
            for (int ks = 0; ks < 2; ks++)
                offA[im][ks] = (u32)((rA + im * 16) * ROWB + (ks * 2 + cA) * 16);
    }
    // B fragments: pair of n8 tiles per ldsm_x4
    u32 offBP[2][2];
    {
        const int rB = wn * 32 + ((lane >> 4) & 1) * 8 + (lane & 7);
        const int cB = (lane >> 3) & 1;
        #pragma unroll
        for (int p = 0; p < 2; p++)
            #pragma unroll
            for (int ks = 0; ks < 2; ks++)
                offBP[p][ks] = (u32)((rB + p * 16) * ROWB + (ks * 2 + cB) * 16);
    }

    float acc[4][4][4];
    #pragma unroll
    for (int im = 0; im < 4; im++)
        #pragma unroll
        for (int in = 0; in < 4; in++)
            #pragma unroll
            for (int q = 0; q < 4; q++) acc[im][in][q] = 0.f;

    const int nt = K >> 5;

    #pragma unroll
    for (int p = 0; p < 2; p++) {
        const int k0 = p * KTILE;
        const u32 b = smb + p * STAGEB;
        cpa16(b + OFF_A + so,      gA + k0);
        cpa16(b + OFF_A + so + 16, gA + k0 + 8);
        cpa16(b + OFF_B + so,      gB + k0);
        cpa16(b + OFF_B + so + 16, gB + k0 + 8);
        CPA_COMMIT();
    }

    int cslot = 0, wslot = 2;
    for (int i = 0; i < nt; i++) {
        CPA_WAIT1();
        __syncthreads();

        const int inext = i + 2;
        if (inext < nt) {
            const int k0 = inext * KTILE;
            const u32 b = smb + (u32)wslot * STAGEB;
            cpa16(b + OFF_A + so,      gA + k0);
            cpa16(b + OFF_A + so + 16, gA + k0 + 8);
            cpa16(b + OFF_B + so,      gB + k0);
            cpa16(b + OFF_B + so + 16, gB + k0 + 8);
        }
        CPA_COMMIT();

        const u32 stage = smb + (u32)cslot * STAGEB;
        #pragma unroll
        for (int ks = 0; ks < 2; ks++) {
            u32 a[4][4];
            #pragma unroll
            for (int im = 0; im < 4; im++)
                ldsm_x4(a[im], stage + OFF_A + offA[im][ks]);
            u32 b[2][4];
            #pragma unroll
            for (int p = 0; p < 2; p++)
                ldsm_x4(b[p], stage + OFF_B + offBP[p][ks]);
            #pragma unroll
            for (int im = 0; im < 4; im++)
                #pragma unroll
                for (int in = 0; in < 4; in++)
                    mma16816(acc[im][in], a[im], b[in >> 1] + (in & 1) * 2);
        }
        cslot = (cslot == 2) ? 0 : cslot + 1;
        wslot = (wslot == 2) ? 0 : wslot + 1;
    }

    // ---- epilogue ----
    if (OUTMODE == 2 && wn >= 2) return;   // only cols 0..63 valid
    const int g = lane >> 2;
    const int cb_in = (lane & 3) * 2;
    #pragma unroll
    for (int in = 0; in < 4; in++) {
        const int col = n0 + wn * 32 + in * 8 + cb_in;
        const float bx = bias[col], by = bias[col + 1];
        #pragma unroll
        for (int im = 0; im < 4; im++) {
            const int r0 = m0 + wm * 64 + im * 16 + g;
            const int r1 = r0 + 8;
            float v00 = acc[im][in][0] + bx, v01 = acc[im][in][1] + by;
            float v10 = acc[im][in][2] + bx, v11 = acc[im][in][3] + by;
            if (RELU) {
                v00 = fmaxf(v00, 0.f); v01 = fmaxf(v01, 0.f);
                v10 = fmaxf(v10, 0.f); v11 = fmaxf(v11, 0.f);
            }
            if (OUTMODE == 0) {
                float* o = Cf + (size_t)e * sC;
                float2 a0 = {v00, v01}, a1 = {v10, v11};
                *(float2*)(o + (size_t)r0 * N + col) = a0;
                *(float2*)(o + (size_t)r1 * N + col) = a1;
            } else {
                __half* oh = Ch + (size_t)e * sC;
                __half2 p;
                p.x = __float2half_rn(v00); p.y = __float2half_rn(v01);
                *(__half2*)(oh + (size_t)r0 * N + col) = p;
                p.x = __float2half_rn(v10); p.y = __float2half_rn(v11);
                *(__half2*)(oh + (size_t)r1 * N + col) = p;
            }
        }
    }
}

// ---------------- conversion kernels ----------------
__global__ void k_half(const float* __restrict__ in, __half* __restrict__ out, int n4)
{
    const int i = blockIdx.x * 256 + threadIdx.x;
    if (i >= n4) return;
    const float4 u = ((const float4*)in)[i];
    __half h[4];
    h[0] = __float2half_rn(u.x); h[1] = __float2half_rn(u.y);
    h[2] = __float2half_rn(u.z); h[3] = __float2half_rn(u.w);
    ((uint2*)out)[i] = *(const uint2*)h;
}

// merged: Wk,Wq,Wo fp32->fp16; Wv -> per-head padded [8][128][512]
__global__ void k_half_w(const float* __restrict__ Wk, const float* __restrict__ Wq,
                         const float* __restrict__ Wo, const float* __restrict__ Wv,
                         __half* __restrict__ wk, __half* __restrict__ wq,
                         __half* __restrict__ wo, __half* __restrict__ wvp)
{
    const int y = blockIdx.y;
    const int i = blockIdx.x * 256 + threadIdx.x;
    if (y < 3) {
        const int n4 = DD * DD / 4;
        if (i >= n4) return;
        const float* src = (y == 0) ? Wk : (y == 1) ? Wq : Wo;
        __half* dst = (y == 0) ? wk : (y == 1) ? wq : wo;
        const float4 u = ((const float4*)src)[i];
        __half h[4];
        h[0] = __float2half_rn(u.x); h[1] = __float2half_rn(u.y);
        h[2] = __float2half_rn(u.z); h[3] = __float2half_rn(u.w);
        ((uint2*)dst)[i] = *(const uint2*)h;
    } else {
        const int n4 = NE * 128 * DD / 4;   // 131072
        if (i >= n4) return;
        const int c4  = i & 127;            // column group (4 cols)
        const int row = i >> 7;             // 0..1023
        const int h   = row >> 7, r = row & 127;
        __half hv[4];
        if (r < 64) {
            const float4 u = ((const float4*)Wv)[(size_t)(h * 64 + r) * (DD / 4) + c4];
            hv[0] = __float2half_rn(u.x); hv[1] = __float2half_rn(u.y);
            hv[2] = __float2half_rn(u.z); hv[3] = __float2half_rn(u.w);
        } else {
            hv[0] = hv[1] = hv[2] = hv[3] = __float2half_rn(0.f);
        }
        ((uint2*)wvp)[i] = *(const uint2*)hv;
    }
}

// transpose + convert: in [R,C] fp32 (batched over z) -> out [C,R] fp16
__global__ void k_thalf(const float* __restrict__ in, __half* __restrict__ out,
                        int R, int C)
{
    __shared__ float t[32][33];
    const size_t zo = (size_t)blockIdx.z * R * C;
    const int c0 = blockIdx.x * 32, r0 = blockIdx.y * 32;
    const int tx = threadIdx.x, ty = threadIdx.y;
    #pragma unroll
    for (int rr = ty; rr < 32; rr += 8)
        t[rr][tx] = in[zo + (size_t)(r0 + rr) * C + c0 + tx];
    __syncthreads();
    #pragma unroll
    for (int cc = ty; cc < 32; cc += 8)
        out[zo + (size_t)(c0 + cc) * R + r0 + tx] = __float2half_rn(t[tx][cc]);
}

// ---------------- attention + per-head eo mixing ----------------
// One block per token, warp h = head h. Computes softmax weights p[f] from q,k,
// then writes m[h][n][:] = sum_f p_f * eo[f][n][:]  (512 dims, fp16).
__global__ void attn_mix_kernel(const __half* __restrict__ q,
                                const __half* __restrict__ kbuf,
                                const __half* __restrict__ eo,
                                __half* __restrict__ m,
                                const int* __restrict__ eidPtr)
{
    __shared__ __half2 eo_s[NE][DD / 2];   // 8 KB
    const int n    = blockIdx.x;
    const int tid  = threadIdx.x;
    const int head = tid >> 5;
    const int lane = tid & 31;
    const int eid  = *eidPtr;

    // stage eo[all 8 experts][512] for this token (512 uint4 total, 2/thread)
    #pragma unroll
    for (int t = 0; t < 2; t++) {
        const int j = tid + 256 * t;       // 0..511
        const int f = j >> 6;              // expert
        const int o = (j & 63) * 8;        // half offset within row
        const uint4 v = *(const uint4*)(eo + (size_t)f * NTOK * DD + (size_t)n * DD + o);
        *(uint4*)&eo_s[f][o / 2] = v;
    }

    const int hb = head * 64 + 2 * lane;
    const float2 qv = __half22float2(*(const __half2*)(q + (size_t)n * DD + hb));

    float s[NE];
    #pragma unroll
    for (int f = 0; f < NE; f++) {
        const float2 kv = __half22float2(
            *(const __half2*)(kbuf + (size_t)f * NTOK * DD + (size_t)n * DD + hb));
        float p = qv.x * kv.x + qv.y * kv.y;
        #pragma unroll
        for (int off = 16; off > 0; off >>= 1)
            p += __shfl_xor_sync(0xffffffffu, p, off);
        s[f] = p * 0.125f + ((f <= eid) ? 1.0f : 0.0f);
    }

    float mx = s[0];
    #pragma unroll
    for (int f = 1; f < NE; f++) mx = fmaxf(mx, s[f]);
    float sum = 0.f;
    #pragma unroll
    for (int f = 0; f < NE; f++) { s[f] = expf(s[f] - mx); sum += s[f]; }
    const float inv = 1.f / sum;
    #pragma unroll
    for (int f = 0; f < NE; f++) s[f] *= inv;

    __syncthreads();   // eo_s ready

    // mix: each lane handles 8 half2 (16 dims); warp covers all 512 dims
    __half* mh = m + (size_t)head * NTOK * DD + (size_t)n * DD;
    #pragma unroll
    for (int c = 0; c < 8; c++) {
        const int d2 = lane + c * 32;      // half2 index 0..255
        float ax = 0.f, ay = 0.f;
        #pragma unroll
        for (int f = 0; f < NE; f++) {
            const float2 v = __half22float2(eo_s[f][d2]);
            ax += s[f] * v.x; ay += s[f] * v.y;
        }
        __half2 o;
        o.x = __float2half_rn(ax); o.y = __float2half_rn(ay);
        *(__half2*)(mh + 2 * d2) = o;
    }
}

// -----------------------------------------------------------------------------
extern "C" void kernel_launch(void* const* d_in, const int* in_sizes, int n_in,
                              void* d_out, int out_size)
{
    const float* x  = (const float*)d_in[0];
    const float* W1 = (const float*)d_in[1];
    const float* b1 = (const float*)d_in[2];
    const float* W2 = (const float*)d_in[3];
    const float* b2 = (const float*)d_in[4];
    const float* Wq = (const float*)d_in[5];
    const float* bq = (const float*)d_in[6];
    const float* Wk = (const float*)d_in[7];
    const float* bk = (const float*)d_in[8];
    const float* Wv = (const float*)d_in[9];
    const float* bv = (const float*)d_in[10];
    const float* Wo = (const float*)d_in[11];
    const float* bo = (const float*)d_in[12];
    const int*  eid = (const int*)  d_in[13];

    __half *xh, *w1, *w2, *wq, *wk, *wo, *wvp, *hid, *eo, *kb, *mb, *qb, *cx;
    cudaGetSymbolAddress((void**)&xh,  g_x);
    cudaGetSymbolAddress((void**)&w1,  g_w1);
    cudaGetSymbolAddress((void**)&w2,  g_w2);
    cudaGetSymbolAddress((void**)&wq,  g_wq);
    cudaGetSymbolAddress((void**)&wk,  g_wk);
    cudaGetSymbolAddress((void**)&wo,  g_wo);
    cudaGetSymbolAddress((void**)&wvp, g_wvp);
    cudaGetSymbolAddress((void**)&hid, g_hid);
    cudaGetSymbolAddress((void**)&eo,  g_eo);
    cudaGetSymbolAddress((void**)&kb,  g_k);
    cudaGetSymbolAddress((void**)&mb,  g_m);
    cudaGetSymbolAddress((void**)&qb,  g_q);
    cudaGetSymbolAddress((void**)&cx,  g_cx);

    cudaFuncSetAttribute(mma_gemm<0, false>, cudaFuncAttributeMaxDynamicSharedMemorySize, SMEM_BYTES);
    cudaFuncSetAttribute(mma_gemm<1, false>, cudaFuncAttributeMaxDynamicSharedMemorySize, SMEM_BYTES);
    cudaFuncSetAttribute(mma_gemm<1, true>,  cudaFuncAttributeMaxDynamicSharedMemorySize, SMEM_BYTES);
    cudaFuncSetAttribute(mma_gemm<2, false>, cudaFuncAttributeMaxDynamicSharedMemorySize, SMEM_BYTES);

    // ---- launches 1-4: conversions; 5/6 are FFN1/FFN2 ----
    k_half<<<(NTOK * DD / 4 + 255) / 256, 256>>>(x, xh, NTOK * DD / 4);             // 1
    {   // 2: W1 [E,512,2048] -> [E,2048,512]
        dim3 g(DFF / 32, DD / 32, NE), b(32, 8);
        k_thalf<<<g, b>>>(W1, w1, DD, DFF);
    }
    {   // 3: W2 [E,2048,512] -> [E,512,2048]
        dim3 g(DD / 32, DFF / 32, NE), b(32, 8);
        k_thalf<<<g, b>>>(W2, w2, DFF, DD);
    }
    {   // 4: Wk/Wq/Wo convert + Wv padded per-head
        dim3 g(NE * 128 * DD / 4 / 256, 4);
        k_half_w<<<g, 256>>>(Wk, Wq, Wo, Wv, wk, wq, wo, wvp);
    }

    // ---- 5: FFN1: hidden[e] = relu(x @ W1[e] + b1[e]) ----
    mma_gemm<1, true><<<dim3(DFF / 128, NTOK / 128, NE), 256, SMEM_BYTES>>>(
        xh, w1, b1, nullptr, hid,
        DFF, DD, 0, (size_t)DFF * DD, DFF, (size_t)NTOK * DFF, nullptr, 0);

    // ---- 6: FFN2: eo[e] = hidden[e] @ W2[e] + b2[e] ----
    mma_gemm<1, false><<<dim3(DD / 128, NTOK / 128, NE), 256, SMEM_BYTES>>>(
        hid, w2, b2, nullptr, eo,
        DD, DFF, (size_t)NTOK * DFF, (size_t)DD * DFF, DD, (size_t)NTOK * DD, nullptr, 0);

    // ---- K proj only: k[e] = eo[e] @ Wk^T + bk  (fp16 out) ----
    mma_gemm<1, false><<<dim3(DD / 128, NTOK / 128, NE), 256, SMEM_BYTES>>>(
        eo, wk, bk, nullptr, kb,
        DD, DD, (size_t)NTOK * DD, 0, 0, (size_t)NTOK * DD, nullptr, 0);

    // ---- Q proj (expert_id slice only, fp16 out) ----
    mma_gemm<1, false><<<dim3(DD / 128, NTOK / 128, 1), 256, SMEM_BYTES>>>(
        eo, wq, bq, nullptr, qb,
        DD, DD, 0, 0, 0, 0, eid, (size_t)NTOK * DD);

    // ---- attention + mix: m[h] = sum_f p[f] * eo[f] ----
    attn_mix_kernel<<<NTOK, 256>>>(qb, kb, eo, mb, eid);

    // ---- V proj on mixed vectors (per-head, N=64 valid of 128 tile):
    //      ctx[:, h*64 + 0..63] = m[h] @ Wv_h^T + bv[h*64..] ----
    mma_gemm<2, false><<<dim3(1, NTOK / 128, NE), 256, SMEM_BYTES>>>(
        mb, wvp, bv, nullptr, cx,
        DD, DD, (size_t)NTOK * DD, (size_t)128 * DD, 64, 64, nullptr, 0);

    // ---- out proj: d_out = ctx @ Wo^T + bo ----
    mma_gemm<0, false><<<dim3(DD / 128, NTOK / 128, 1), 256, SMEM_BYTES>>>(
        cx, wo, bo, (float*)d_out, nullptr,
        DD, DD, 0, 0, 0, 0, nullptr, 0);
}

// round 15
// speedup vs baseline: 1.1208x; 1.0089x over previous
#include <cuda_runtime.h>
#include <cuda_fp16.h>

typedef unsigned int u32;
typedef unsigned long long u64;

#define NE   8
#define DD   512
#define DFF  2048
#define NTOK 4096

// ---------------- device scratch (no allocation allowed) ----------------
__device__ __half g_x  [(size_t)NTOK*DD];
__device__ __half g_w1 [(size_t)NE*DFF*DD];     // W1^T per expert [2048,512]
__device__ __half g_w2 [(size_t)NE*DD*DFF];     // W2^T per expert [512,2048]
__device__ __half g_wq [DD*DD];
__device__ __half g_wkp[(size_t)NE*DD*64];      // per-head packed Wk^T: [h][n][j]=Wk[h*64+j][n]
__device__ __half g_wo [DD*DD];
__device__ __half g_wvp[(size_t)NE*128*DD];     // Wv per head, padded to 128 rows
__device__ float  g_zerob[DD];                  // zero bias (static zero-init)
__device__ __half g_hid[(size_t)NE*NTOK*DFF];
__device__ __half g_eo [(size_t)NE*NTOK*DD];
__device__ __half g_r  [(size_t)NE*NTOK*DD];    // r[h][n][d] = q_h[n] @ Wk_h
__device__ __half g_m  [(size_t)NE*NTOK*DD];    // per-head mixed eo
__device__ __half g_q  [(size_t)NTOK*DD];       // fp16 q (expert_id slice)
__device__ __half g_cx [(size_t)NTOK*DD];

// ---------------- helpers ----------------
__device__ __forceinline__ u32 smem_u32(const void* p) {
    return (u32)__cvta_generic_to_shared(p);
}
__device__ __forceinline__ void cpa16(u32 dst, const void* src) {
    asm volatile("cp.async.cg.shared.global [%0], [%1], 16;" :: "r"(dst), "l"(src));
}
#define CPA_COMMIT() asm volatile("cp.async.commit_group;" ::: "memory")
#define CPA_WAIT1()  asm volatile("cp.async.wait_group 1;" ::: "memory")

__device__ __forceinline__ void ldsm_x4(u32* r, u32 addr) {
    asm volatile("ldmatrix.sync.aligned.m8n8.x4.shared.b16 {%0,%1,%2,%3}, [%4];"
                 : "=r"(r[0]), "=r"(r[1]), "=r"(r[2]), "=r"(r[3]) : "r"(addr));
}
__device__ __forceinline__ void mma16816(float* c, const u32* a, const u32* b) {
    asm volatile(
        "mma.sync.aligned.m16n8k16.row.col.f32.f16.f16.f32 "
        "{%0,%1,%2,%3}, {%4,%5,%6,%7}, {%8,%9}, {%0,%1,%2,%3};"
        : "+f"(c[0]), "+f"(c[1]), "+f"(c[2]), "+f"(c[3])
        : "r"(a[0]), "r"(a[1]), "r"(a[2]), "r"(a[3]), "r"(b[0]), "r"(b[1]));
}

// smem geometry: tile 128x128, ktile 32 (64B/row + 16 pad = 80B rows), slabs A,B
#define KTILE   32
#define ROWB    80
#define OFF_A   0
#define OFF_B   (128*ROWB)           // 10240
#define STAGEB  (2*128*ROWB)         // 20480
#define NSTAGE  3
#define SMEM_BYTES (NSTAGE * STAGEB) // 61440 -> 2 CTAs/SM

// ---------------- fp16 mma.sync GEMM ----------------
// D[m,n] = sum_k A[m,k]*B[n,k] + bias[n]. A row stride lda (>= K), B packed (K).
// OUTMODE: 0 -> fp32 Cf; 1 -> fp16 Ch; 2 -> fp16 Ch, only cols 0..63 valid
// (warps wn>=2 skip epilogue; e*sC is a COLUMN offset, ld = N).
template<int OUTMODE, bool RELU>
__global__ void __launch_bounds__(256, 2) mma_gemm(
    const __half* __restrict__ A, const __half* __restrict__ B,
    const float* __restrict__ biasg,
    float* __restrict__ Cf, __half* __restrict__ Ch,
    int N, int K, int lda,
    size_t sA, size_t sB, size_t sBias, size_t sC,
    const int* __restrict__ eidPtr, size_t eidStride)
{
    extern __shared__ __align__(128) char sm[];
    const int tid  = threadIdx.x;
    const int lane = tid & 31;
    const int wid  = tid >> 5;
    const int e    = blockIdx.z;
    const int m0   = blockIdx.y * 128;
    const int n0   = blockIdx.x * 128;

    size_t aoff = (size_t)e * sA;
    if (eidPtr) aoff += (size_t)(*eidPtr) * eidStride;
    const __half* pA = A + aoff;
    const __half* pB = B + (size_t)e * sB;
    const float* bias = biasg + (size_t)e * sBias;

    const u32 smb = smem_u32(sm);

    // ---- loader mapping: 128 rows x 64B/slab, 2 threads/row, 2x16B per slab ----
    const int lr = tid >> 1;
    const int lc = (tid & 1) * 2;
    const __half* gA = pA + (size_t)(m0 + lr) * lda + lc * 8;
    const __half* gB = pB + (size_t)(n0 + lr) * K + lc * 8;
    const u32 so = (u32)(lr * ROWB + lc * 16);

    // ---- warp/compute mapping: warps 2x4, warp tile 64x32 ----
    const int wm = wid >> 2;
    const int wn = wid & 3;

    u32 offA[4][2];
    {
        const int rA = wm * 64 + (lane & 15);
        const int cA = lane >> 4;
        #pragma unroll
        for (int im = 0; im < 4; im++)
            #pragma unroll
            for (int ks = 0; ks < 2; ks++)
                offA[im][ks] = (u32)((rA + im * 16) * ROWB + (ks * 2 + cA) * 16);
    }
    u32 offBP[2][2];
    {
        const int rB = wn * 32 + ((lane >> 4) & 1) * 8 + (lane & 7);
        const int cB = (lane >> 3) & 1;
        #pragma unroll
        for (int p = 0; p < 2; p++)
            #pragma unroll
            for (int ks = 0; ks < 2; ks++)
                offBP[p][ks] = (u32)((rB + p * 16) * ROWB + (ks * 2 + cB) * 16);
    }

    float acc[4][4][4];
    #pragma unroll
    for (int im = 0; im < 4; im++)
        #pragma unroll
        for (int in = 0; in < 4; in++)
            #pragma unroll
            for (int q = 0; q < 4; q++) acc[im][in][q] = 0.f;

    const int nt = K >> 5;

    #pragma unroll
    for (int p = 0; p < 2; p++) {
        const int k0 = p * KTILE;
        const u32 b = smb + p * STAGEB;
        cpa16(b + OFF_A + so,      gA + k0);
        cpa16(b + OFF_A + so + 16, gA + k0 + 8);
        cpa16(b + OFF_B + so,      gB + k0);
        cpa16(b + OFF_B + so + 16, gB + k0 + 8);
        CPA_COMMIT();
    }

    int cslot = 0, wslot = 2;
    for (int i = 0; i < nt; i++) {
        CPA_WAIT1();
        __syncthreads();

        const int inext = i + 2;
        if (inext < nt) {
            const int k0 = inext * KTILE;
            const u32 b = smb + (u32)wslot * STAGEB;
            cpa16(b + OFF_A + so,      gA + k0);
            cpa16(b + OFF_A + so + 16, gA + k0 + 8);
            cpa16(b + OFF_B + so,      gB + k0);
            cpa16(b + OFF_B + so + 16, gB + k0 + 8);
        }
        CPA_COMMIT();

        const u32 stage = smb + (u32)cslot * STAGEB;
        #pragma unroll
        for (int ks = 0; ks < 2; ks++) {
            u32 a[4][4];
            #pragma unroll
            for (int im = 0; im < 4; im++)
                ldsm_x4(a[im], stage + OFF_A + offA[im][ks]);
            u32 b[2][4];
            #pragma unroll
            for (int p = 0; p < 2; p++)
                ldsm_x4(b[p], stage + OFF_B + offBP[p][ks]);
            #pragma unroll
            for (int im = 0; im < 4; im++)
                #pragma unroll
                for (int in = 0; in < 4; in++)
                    mma16816(acc[im][in], a[im], b[in >> 1] + (in & 1) * 2);
        }
        cslot = (cslot == 2) ? 0 : cslot + 1;
        wslot = (wslot == 2) ? 0 : wslot + 1;
    }

    // ---- epilogue ----
    if (OUTMODE == 2 && wn >= 2) return;
    const int g = lane >> 2;
    const int cb_in = (lane & 3) * 2;
    #pragma unroll
    for (int in = 0; in < 4; in++) {
        const int col = n0 + wn * 32 + in * 8 + cb_in;
        const float bx = bias[col], by = bias[col + 1];
        #pragma unroll
        for (int im = 0; im < 4; im++) {
            const int r0 = m0 + wm * 64 + im * 16 + g;
            const int r1 = r0 + 8;
            float v00 = acc[im][in][0] + bx, v01 = acc[im][in][1] + by;
            float v10 = acc[im][in][2] + bx, v11 = acc[im][in][3] + by;
            if (RELU) {
                v00 = fmaxf(v00, 0.f); v01 = fmaxf(v01, 0.f);
                v10 = fmaxf(v10, 0.f); v11 = fmaxf(v11, 0.f);
            }
            if (OUTMODE == 0) {
                float* o = Cf + (size_t)e * sC;
                float2 a0 = {v00, v01}, a1 = {v10, v11};
                *(float2*)(o + (size_t)r0 * N + col) = a0;
                *(float2*)(o + (size_t)r1 * N + col) = a1;
            } else {
                __half* oh = Ch + (size_t)e * sC;
                __half2 p;
                p.x = __float2half_rn(v00); p.y = __float2half_rn(v01);
                *(__half2*)(oh + (size_t)r0 * N + col) = p;
                p.x = __float2half_rn(v10); p.y = __float2half_rn(v11);
                *(__half2*)(oh + (size_t)r1 * N + col) = p;
            }
        }
    }
}

// ---------------- conversion kernels ----------------
__global__ void k_half(const float* __restrict__ in, __half* __restrict__ out, int n4)
{
    const int i = blockIdx.x * 256 + threadIdx.x;
    if (i >= n4) return;
    const float4 u = ((const float4*)in)[i];
    __half h[4];
    h[0] = __float2half_rn(u.x); h[1] = __float2half_rn(u.y);
    h[2] = __float2half_rn(u.z); h[3] = __float2half_rn(u.w);
    ((uint2*)out)[i] = *(const uint2*)h;
}

// merged: Wq,Wo fp32->fp16; Wv -> per-head padded [8][128][512]
__global__ void k_half_w(const float* __restrict__ Wq, const float* __restrict__ Wo,
                         const float* __restrict__ Wv,
                         __half* __restrict__ wq, __half* __restrict__ wo,
                         __half* __restrict__ wvp)
{
    const int y = blockIdx.y;
    const int i = blockIdx.x * 256 + threadIdx.x;
    if (y < 2) {
        const int n4 = DD * DD / 4;
        if (i >= n4) return;
        const float* src = (y == 0) ? Wq : Wo;
        __half* dst = (y == 0) ? wq : wo;
        const float4 u = ((const float4*)src)[i];
        __half h[4];
        h[0] = __float2half_rn(u.x); h[1] = __float2half_rn(u.y);
        h[2] = __float2half_rn(u.z); h[3] = __float2half_rn(u.w);
        ((uint2*)dst)[i] = *(const uint2*)h;
    } else {
        const int n4 = NE * 128 * DD / 4;
        if (i >= n4) return;
        const int c4  = i & 127;
        const int row = i >> 7;
        const int h   = row >> 7, r = row & 127;
        __half hv[4];
        if (r < 64) {
            const float4 u = ((const float4*)Wv)[(size_t)(h * 64 + r) * (DD / 4) + c4];
            hv[0] = __float2half_rn(u.x); hv[1] = __float2half_rn(u.y);
            hv[2] = __float2half_rn(u.z); hv[3] = __float2half_rn(u.w);
        } else {
            hv[0] = hv[1] = hv[2] = hv[3] = __float2half_rn(0.f);
        }
        ((uint2*)wvp)[i] = *(const uint2*)hv;
    }
}

// pack Wk^T per head: wkp[h][n][j] = Wk[h*64+j][n]
__global__ void k_wk_pack(const float* __restrict__ Wk, __half* __restrict__ wkp)
{
    __shared__ float t[32][33];
    const int c0 = blockIdx.x * 32;   // n (col of Wk)
    const int r0 = blockIdx.y * 32;   // jglobal (row of Wk)
    const int tx = threadIdx.x, ty = threadIdx.y;
    #pragma unroll
    for (int rr = ty; rr < 32; rr += 8)
        t[rr][tx] = Wk[(size_t)(r0 + rr) * DD + c0 + tx];
    __syncthreads();
    #pragma unroll
    for (int cc = ty; cc < 32; cc += 8) {
        const int jg = r0 + cc;
        const int n  = c0 + tx;
        // value must be Wk[jg][n] = Wk[r0+cc][c0+tx] = t[cc][tx]  (bug fix)
        wkp[((size_t)(jg >> 6) * DD + n) * 64 + (jg & 63)] = __float2half_rn(t[cc][tx]);
    }
}

// transpose + convert: in [R,C] fp32 (batched over z) -> out [C,R] fp16
__global__ void k_thalf(const float* __restrict__ in, __half* __restrict__ out,
                        int R, int C)
{
    __shared__ float t[32][33];
    const size_t zo = (size_t)blockIdx.z * R * C;
    const int c0 = blockIdx.x * 32, r0 = blockIdx.y * 32;
    const int tx = threadIdx.x, ty = threadIdx.y;
    #pragma unroll
    for (int rr = ty; rr < 32; rr += 8)
        t[rr][tx] = in[zo + (size_t)(r0 + rr) * C + c0 + tx];
    __syncthreads();
    #pragma unroll
    for (int cc = ty; cc < 32; cc += 8)
        out[zo + (size_t)(c0 + cc) * R + r0 + tx] = __float2half_rn(t[tx][cc]);
}

// ---------------- attention (via r·eo) + per-head eo mixing ----------------
// s_f[h] = (r_h·eo_f + q_h·bk_h)/8 + mask; m[h] = sum_f softmax(s)_f * eo_f
__global__ void attn_mix_kernel(const __half* __restrict__ q,
                                const __half* __restrict__ rb,
                                const __half* __restrict__ eo,
                                const float* __restrict__ bk,
                                __half* __restrict__ m,
                                const int* __restrict__ eidPtr)
{
    __shared__ __half2 eo_s[NE][DD / 2];   // 8 KB
    __shared__ __half2 r_s [NE][DD / 2];   // 8 KB
    const int n    = blockIdx.x;
    const int tid  = threadIdx.x;
    const int head = tid >> 5;
    const int lane = tid & 31;
    const int eid  = *eidPtr;

    #pragma unroll
    for (int t = 0; t < 2; t++) {
        const int j = tid + 256 * t;       // 0..511
        const int f = j >> 6;
        const int o = (j & 63) * 8;
        *(uint4*)&eo_s[f][o / 2] =
            *(const uint4*)(eo + (size_t)f * NTOK * DD + (size_t)n * DD + o);
        *(uint4*)&r_s[f][o / 2] =
            *(const uint4*)(rb + (size_t)f * NTOK * DD + (size_t)n * DD + o);
    }

    // c_h = q_h . bk_h
    const int hb = head * 64 + 2 * lane;
    const float2 qv = __half22float2(*(const __half2*)(q + (size_t)n * DD + hb));
    float ch = qv.x * bk[hb] + qv.y * bk[hb + 1];
    #pragma unroll
    for (int off = 16; off > 0; off >>= 1)
        ch += __shfl_xor_sync(0xffffffffu, ch, off);

    __syncthreads();   // eo_s / r_s ready

    float s[NE];
    #pragma unroll
    for (int f = 0; f < NE; f++) {
        float p = 0.f;
        #pragma unroll
        for (int c = 0; c < 8; c++) {
            const int d2 = lane + c * 32;
            const float2 rv = __half22float2(r_s[head][d2]);
            const float2 ev = __half22float2(eo_s[f][d2]);
            p += rv.x * ev.x + rv.y * ev.y;
        }
        #pragma unroll
        for (int off = 16; off > 0; off >>= 1)
            p += __shfl_xor_sync(0xffffffffu, p, off);
        s[f] = (p + ch) * 0.125f + ((f <= eid) ? 1.0f : 0.0f);
    }

    float mx = s[0];
    #pragma unroll
    for (int f = 1; f < NE; f++) mx = fmaxf(mx, s[f]);
    float sum = 0.f;
    #pragma unroll
    for (int f = 0; f < NE; f++) { s[f] = expf(s[f] - mx); sum += s[f]; }
    const float inv = 1.f / sum;
    #pragma unroll
    for (int f = 0; f < NE; f++) s[f] *= inv;

    __half* mh = m + (size_t)head * NTOK * DD + (size_t)n * DD;
    #pragma unroll
    for (int c = 0; c < 8; c++) {
        const int d2 = lane + c * 32;
        float ax = 0.f, ay = 0.f;
        #pragma unroll
        for (int f = 0; f < NE; f++) {
            const float2 v = __half22float2(eo_s[f][d2]);
            ax += s[f] * v.x; ay += s[f] * v.y;
        }
        __half2 o;
        o.x = __float2half_rn(ax); o.y = __float2half_rn(ay);
        *(__half2*)(mh + 2 * d2) = o;
    }
}

// -----------------------------------------------------------------------------
extern "C" void kernel_launch(void* const* d_in, const int* in_sizes, int n_in,
                              void* d_out, int out_size)
{
    const float* x  = (const float*)d_in[0];
    const float* W1 = (const float*)d_in[1];
    const float* b1 = (const float*)d_in[2];
    const float* W2 = (const float*)d_in[3];
    const float* b2 = (const float*)d_in[4];
    const float* Wq = (const float*)d_in[5];
    const float* bq = (const float*)d_in[6];
    const float* Wk = (const float*)d_in[7];
    const float* bk = (const float*)d_in[8];
    const float* Wv = (const float*)d_in[9];
    const float* bv = (const float*)d_in[10];
    const float* Wo = (const float*)d_in[11];
    const float* bo = (const float*)d_in[12];
    const int*  eid = (const int*)  d_in[13];

    __half *xh, *w1, *w2, *wq, *wkp, *wo, *wvp, *hid, *eo, *rb, *mb, *qb, *cx;
    float *zb;
    cudaGetSymbolAddress((void**)&xh,  g_x);
    cudaGetSymbolAddress((void**)&w1,  g_w1);
    cudaGetSymbolAddress((void**)&w2,  g_w2);
    cudaGetSymbolAddress((void**)&wq,  g_wq);
    cudaGetSymbolAddress((void**)&wkp, g_wkp);
    cudaGetSymbolAddress((void**)&wo,  g_wo);
    cudaGetSymbolAddress((void**)&wvp, g_wvp);
    cudaGetSymbolAddress((void**)&hid, g_hid);
    cudaGetSymbolAddress((void**)&eo,  g_eo);
    cudaGetSymbolAddress((void**)&rb,  g_r);
    cudaGetSymbolAddress((void**)&mb,  g_m);
    cudaGetSymbolAddress((void**)&qb,  g_q);
    cudaGetSymbolAddress((void**)&cx,  g_cx);
    cudaGetSymbolAddress((void**)&zb,  g_zerob);

    cudaFuncSetAttribute(mma_gemm<0, false>, cudaFuncAttributeMaxDynamicSharedMemorySize, SMEM_BYTES);
    cudaFuncSetAttribute(mma_gemm<1, false>, cudaFuncAttributeMaxDynamicSharedMemorySize, SMEM_BYTES);
    cudaFuncSetAttribute(mma_gemm<1, true>,  cudaFuncAttributeMaxDynamicSharedMemorySize, SMEM_BYTES);
    cudaFuncSetAttribute(mma_gemm<2, false>, cudaFuncAttributeMaxDynamicSharedMemorySize, SMEM_BYTES);

    // ---- conversions ----
    k_half<<<(NTOK * DD / 4 + 255) / 256, 256>>>(x, xh, NTOK * DD / 4);
    {   // W1 [E,512,2048] -> [E,2048,512]
        dim3 g(DFF / 32, DD / 32, NE), b(32, 8);
        k_thalf<<<g, b>>>(W1, w1, DD, DFF);
    }
    {   // W2 [E,2048,512] -> [E,512,2048]
        dim3 g(DD / 32, DFF / 32, NE), b(32, 8);
        k_thalf<<<g, b>>>(W2, w2, DFF, DD);
    }
    {   // Wq/Wo convert + Wv padded per-head
        dim3 g(NE * 128 * DD / 4 / 256, 3);
        k_half_w<<<g, 256>>>(Wq, Wo, Wv, wq, wo, wvp);
    }
    {   // Wk^T packed per head
        dim3 g(DD / 32, DD / 32), b(32, 8);
        k_wk_pack<<<g, b>>>(Wk, wkp);
    }

    // ---- FFN1: hidden[e] = relu(x @ W1[e] + b1[e]) ----
    mma_gemm<1, true><<<dim3(DFF / 128, NTOK / 128, NE), 256, SMEM_BYTES>>>(
        xh, w1, b1, nullptr, hid,
        DFF, DD, DD, 0, (size_t)DFF * DD, DFF, (size_t)NTOK * DFF, nullptr, 0);

    // ---- FFN2: eo[e] = hidden[e] @ W2[e] + b2[e] ----
    mma_gemm<1, false><<<dim3(DD / 128, NTOK / 128, NE), 256, SMEM_BYTES>>>(
        hid, w2, b2, nullptr, eo,
        DD, DFF, DFF, (size_t)NTOK * DFF, (size_t)DD * DFF, DD, (size_t)NTOK * DD, nullptr, 0);

    // ---- Q proj (expert_id slice only, fp16 out) ----
    mma_gemm<1, false><<<dim3(DD / 128, NTOK / 128, 1), 256, SMEM_BYTES>>>(
        eo, wq, bq, nullptr, qb,
        DD, DD, DD, 0, 0, 0, 0, eid, (size_t)NTOK * DD);

    // ---- r GEMM: r[h] = q[:, h*64:(h+1)*64] @ Wk_h  (M=4096, N=512, K=64) ----
    mma_gemm<1, false><<<dim3(DD / 128, NTOK / 128, NE), 256, SMEM_BYTES>>>(
        qb, wkp, zb, nullptr, rb,
        DD, 64, DD, 64 /*sA = column offset per head*/, (size_t)DD * 64, 0,
        (size_t)NTOK * DD, nullptr, 0);

    // ---- attention (r·eo scores) + mix ----
    attn_mix_kernel<<<NTOK, 256>>>(qb, rb, eo, bk, mb, eid);

    // ---- V proj on mixed vectors (per-head, N=64 valid of 128 tile) ----
    mma_gemm<2, false><<<dim3(1, NTOK / 128, NE), 256, SMEM_BYTES>>>(
        mb, wvp, bv, nullptr, cx,
        DD, DD, DD, (size_t)NTOK * DD, (size_t)128 * DD, 64, 64, nullptr, 0);

    // ---- out proj: d_out = ctx @ Wo^T + bo ----
    mma_gemm<0, false><<<dim3(DD / 128, NTOK / 128, 1), 256, SMEM_BYTES>>>(
        cx, wo, bo, (float*)d_out, nullptr,
        DD, DD, DD, 0, 0, 0, 0, nullptr, 0);
}

// round 16
// speedup vs baseline: 1.1415x; 1.0184x over previous
#include <cuda_runtime.h>
#include <cuda_fp16.h>

typedef unsigned int u32;
typedef unsigned long long u64;

#define NE   8
#define DD   512
#define DFF  2048
#define NTOK 4096

// ---------------- device scratch (no allocation allowed) ----------------
__device__ __half g_x  [(size_t)NTOK*DD];
__device__ __half g_w1 [(size_t)NE*DFF*DD];     // W1^T per expert [2048,512]
__device__ __half g_w2 [(size_t)NE*DD*DFF];     // W2^T per expert [512,2048]
__device__ __half g_wq [DD*DD];
__device__ __half g_wkp[(size_t)NE*DD*64];      // per-head packed Wk^T: [h][n][j]=Wk[h*64+j][n]
__device__ __half g_wo [DD*DD];
__device__ __half g_wvp[(size_t)NE*128*DD];     // Wv per head, padded to 128 rows
__device__ float  g_zerob[DD];                  // zero bias (static zero-init)
__device__ __half g_hid[(size_t)NE*NTOK*DFF];
__device__ __half g_eo [(size_t)NE*NTOK*DD];
__device__ __half g_r  [(size_t)NE*NTOK*DD];    // r[h][n][d] = q_h[n] @ Wk_h
__device__ __half g_m  [(size_t)NE*NTOK*DD];    // per-head mixed eo
__device__ __half g_q  [(size_t)NTOK*DD];       // fp16 q (expert_id slice)
__device__ __half g_cx [(size_t)NTOK*DD];

// ---------------- helpers ----------------
__device__ __forceinline__ u32 smem_u32(const void* p) {
    return (u32)__cvta_generic_to_shared(p);
}
__device__ __forceinline__ void cpa16(u32 dst, const void* src) {
    asm volatile("cp.async.cg.shared.global [%0], [%1], 16;" :: "r"(dst), "l"(src));
}
#define CPA_COMMIT() asm volatile("cp.async.commit_group;" ::: "memory")
#define CPA_WAIT1()  asm volatile("cp.async.wait_group 1;" ::: "memory")

__device__ __forceinline__ void ldsm_x4(u32* r, u32 addr) {
    asm volatile("ldmatrix.sync.aligned.m8n8.x4.shared.b16 {%0,%1,%2,%3}, [%4];"
                 : "=r"(r[0]), "=r"(r[1]), "=r"(r[2]), "=r"(r[3]) : "r"(addr));
}
__device__ __forceinline__ void mma16816(float* c, const u32* a, const u32* b) {
    asm volatile(
        "mma.sync.aligned.m16n8k16.row.col.f32.f16.f16.f32 "
        "{%0,%1,%2,%3}, {%4,%5,%6,%7}, {%8,%9}, {%0,%1,%2,%3};"
        : "+f"(c[0]), "+f"(c[1]), "+f"(c[2]), "+f"(c[3])
        : "r"(a[0]), "r"(a[1]), "r"(a[2]), "r"(a[3]), "r"(b[0]), "r"(b[1]));
}

// smem geometry: tile 128x128, ktile 32 (64B/row + 16 pad = 80B rows), slabs A,B
#define KTILE   32
#define ROWB    80
#define OFF_A   0
#define OFF_B   (128*ROWB)           // 10240
#define STAGEB  (2*128*ROWB)         // 20480
#define NSTAGE  3
#define SMEM_BYTES (NSTAGE * STAGEB) // 61440 -> 2 CTAs/SM

// ---------------- fp16 mma.sync GEMM ----------------
// D[m,n] = sum_k A[m,k]*B[n,k] + bias[n]. A row stride lda (>= K), B packed (K).
// OUTMODE: 0 -> fp32 Cf; 1 -> fp16 Ch; 2 -> fp16 Ch, only cols 0..63 valid
// (warps wn>=2 skip epilogue; e*sC is a COLUMN offset, ld = N).
template<int OUTMODE, bool RELU>
__global__ void __launch_bounds__(256, 2) mma_gemm(
    const __half* __restrict__ A, const __half* __restrict__ B,
    const float* __restrict__ biasg,
    float* __restrict__ Cf, __half* __restrict__ Ch,
    int N, int K, int lda,
    size_t sA, size_t sB, size_t sBias, size_t sC,
    const int* __restrict__ eidPtr, size_t eidStride)
{
    extern __shared__ __align__(128) char sm[];
    const int tid  = threadIdx.x;
    const int lane = tid & 31;
    const int wid  = tid >> 5;
    const int e    = blockIdx.z;
    const int m0   = blockIdx.y * 128;
    const int n0   = blockIdx.x * 128;

    size_t aoff = (size_t)e * sA;
    if (eidPtr) aoff += (size_t)(*eidPtr) * eidStride;
    const __half* pA = A + aoff;
    const __half* pB = B + (size_t)e * sB;
    const float* bias = biasg + (size_t)e * sBias;

    const u32 smb = smem_u32(sm);

    // ---- loader mapping: 128 rows x 64B/slab, 2 threads/row, 2x16B per slab ----
    const int lr = tid >> 1;
    const int lc = (tid & 1) * 2;
    const __half* gA = pA + (size_t)(m0 + lr) * lda + lc * 8;
    const __half* gB = pB + (size_t)(n0 + lr) * K + lc * 8;
    const u32 so = (u32)(lr * ROWB + lc * 16);

    // ---- warp/compute mapping: warps 2x4, warp tile 64x32 ----
    const int wm = wid >> 2;
    const int wn = wid & 3;

    u32 offA[4][2];
    {
        const int rA = wm * 64 + (lane & 15);
        const int cA = lane >> 4;
        #pragma unroll
        for (int im = 0; im < 4; im++)
            #pragma unroll
            for (int ks = 0; ks < 2; ks++)
                offA[im][ks] = (u32)((rA + im * 16) * ROWB + (ks * 2 + cA) * 16);
    }
    u32 offBP[2][2];
    {
        const int rB = wn * 32 + ((lane >> 4) & 1) * 8 + (lane & 7);
        const int cB = (lane >> 3) & 1;
        #pragma unroll
        for (int p = 0; p < 2; p++)
            #pragma unroll
            for (int ks = 0; ks < 2; ks++)
                offBP[p][ks] = (u32)((rB + p * 16) * ROWB + (ks * 2 + cB) * 16);
    }

    float acc[4][4][4];
    #pragma unroll
    for (int im = 0; im < 4; im++)
        #pragma unroll
        for (int in = 0; in < 4; in++)
            #pragma unroll
            for (int q = 0; q < 4; q++) acc[im][in][q] = 0.f;

    const int nt = K >> 5;

    #pragma unroll
    for (int p = 0; p < 2; p++) {
        const int k0 = p * KTILE;
        const u32 b = smb + p * STAGEB;
        cpa16(b + OFF_A + so,      gA + k0);
        cpa16(b + OFF_A + so + 16, gA + k0 + 8);
        cpa16(b + OFF_B + so,      gB + k0);
        cpa16(b + OFF_B + so + 16, gB + k0 + 8);
        CPA_COMMIT();
    }

    int cslot = 0, wslot = 2;
    for (int i = 0; i < nt; i++) {
        CPA_WAIT1();
        __syncthreads();

        const int inext = i + 2;
        if (inext < nt) {
            const int k0 = inext * KTILE;
            const u32 b = smb + (u32)wslot * STAGEB;
            cpa16(b + OFF_A + so,      gA + k0);
            cpa16(b + OFF_A + so + 16, gA + k0 + 8);
            cpa16(b + OFF_B + so,      gB + k0);
            cpa16(b + OFF_B + so + 16, gB + k0 + 8);
        }
        CPA_COMMIT();

        const u32 stage = smb + (u32)cslot * STAGEB;
        #pragma unroll
        for (int ks = 0; ks < 2; ks++) {
            u32 a[4][4];
            #pragma unroll
            for (int im = 0; im < 4; im++)
                ldsm_x4(a[im], stage + OFF_A + offA[im][ks]);
            u32 b[2][4];
            #pragma unroll
            for (int p = 0; p < 2; p++)
                ldsm_x4(b[p], stage + OFF_B + offBP[p][ks]);
            #pragma unroll
            for (int im = 0; im < 4; im++)
                #pragma unroll
                for (int in = 0; in < 4; in++)
                    mma16816(acc[im][in], a[im], b[in >> 1] + (in & 1) * 2);
        }
        cslot = (cslot == 2) ? 0 : cslot + 1;
        wslot = (wslot == 2) ? 0 : wslot + 1;
    }

    // ---- epilogue ----
    if (OUTMODE == 2 && wn >= 2) return;
    const int g = lane >> 2;
    const int cb_in = (lane & 3) * 2;
    #pragma unroll
    for (int in = 0; in < 4; in++) {
        const int col = n0 + wn * 32 + in * 8 + cb_in;
        const float bx = bias[col], by = bias[col + 1];
        #pragma unroll
        for (int im = 0; im < 4; im++) {
            const int r0 = m0 + wm * 64 + im * 16 + g;
            const int r1 = r0 + 8;
            float v00 = acc[im][in][0] + bx, v01 = acc[im][in][1] + by;
            float v10 = acc[im][in][2] + bx, v11 = acc[im][in][3] + by;
            if (RELU) {
                v00 = fmaxf(v00, 0.f); v01 = fmaxf(v01, 0.f);
                v10 = fmaxf(v10, 0.f); v11 = fmaxf(v11, 0.f);
            }
            if (OUTMODE == 0) {
                float* o = Cf + (size_t)e * sC;
                float2 a0 = {v00, v01}, a1 = {v10, v11};
                *(float2*)(o + (size_t)r0 * N + col) = a0;
                *(float2*)(o + (size_t)r1 * N + col) = a1;
            } else {
                __half* oh = Ch + (size_t)e * sC;
                __half2 p;
                p.x = __float2half_rn(v00); p.y = __float2half_rn(v01);
                *(__half2*)(oh + (size_t)r0 * N + col) = p;
                p.x = __float2half_rn(v10); p.y = __float2half_rn(v11);
                *(__half2*)(oh + (size_t)r1 * N + col) = p;
            }
        }
    }
}

// ---------------- conversion kernels ----------------
__global__ void k_half(const float* __restrict__ in, __half* __restrict__ out, int n4)
{
    const int i = blockIdx.x * 256 + threadIdx.x;
    if (i >= n4) return;
    const float4 u = ((const float4*)in)[i];
    __half h[4];
    h[0] = __float2half_rn(u.x); h[1] = __float2half_rn(u.y);
    h[2] = __float2half_rn(u.z); h[3] = __float2half_rn(u.w);
    ((uint2*)out)[i] = *(const uint2*)h;
}

// merged: Wq,Wo fp32->fp16; Wv -> per-head padded [8][128][512]
__global__ void k_half_w(const float* __restrict__ Wq, const float* __restrict__ Wo,
                         const float* __restrict__ Wv,
                         __half* __restrict__ wq, __half* __restrict__ wo,
                         __half* __restrict__ wvp)
{
    const int y = blockIdx.y;
    const int i = blockIdx.x * 256 + threadIdx.x;
    if (y < 2) {
        const int n4 = DD * DD / 4;
        if (i >= n4) return;
        const float* src = (y == 0) ? Wq : Wo;
        __half* dst = (y == 0) ? wq : wo;
        const float4 u = ((const float4*)src)[i];
        __half h[4];
        h[0] = __float2half_rn(u.x); h[1] = __float2half_rn(u.y);
        h[2] = __float2half_rn(u.z); h[3] = __float2half_rn(u.w);
        ((uint2*)dst)[i] = *(const uint2*)h;
    } else {
        const int n4 = NE * 128 * DD / 4;
        if (i >= n4) return;
        const int c4  = i & 127;
        const int row = i >> 7;
        const int h   = row >> 7, r = row & 127;
        __half hv[4];
        if (r < 64) {
            const float4 u = ((const float4*)Wv)[(size_t)(h * 64 + r) * (DD / 4) + c4];
            hv[0] = __float2half_rn(u.x); hv[1] = __float2half_rn(u.y);
            hv[2] = __float2half_rn(u.z); hv[3] = __float2half_rn(u.w);
        } else {
            hv[0] = hv[1] = hv[2] = hv[3] = __float2half_rn(0.f);
        }
        ((uint2*)wvp)[i] = *(const uint2*)hv;
    }
}

// pack Wk^T per head: wkp[h][n][j] = Wk[h*64+j][n]
__global__ void k_wk_pack(const float* __restrict__ Wk, __half* __restrict__ wkp)
{
    __shared__ float t[32][33];
    const int c0 = blockIdx.x * 32;   // n (col of Wk)
    const int r0 = blockIdx.y * 32;   // jglobal (row of Wk)
    const int tx = threadIdx.x, ty = threadIdx.y;
    #pragma unroll
    for (int rr = ty; rr < 32; rr += 8)
        t[rr][tx] = Wk[(size_t)(r0 + rr) * DD + c0 + tx];
    __syncthreads();
    #pragma unroll
    for (int cc = ty; cc < 32; cc += 8) {
        const int jg = r0 + cc;
        const int n  = c0 + tx;
        wkp[((size_t)(jg >> 6) * DD + n) * 64 + (jg & 63)] = __float2half_rn(t[cc][tx]);
    }
}

// transpose + convert, vectorized writes: in [R,C] fp32 (batched z) -> out [C,R] fp16
// 64(R) x 32(C) tile; output row (fixed c) = 64 contiguous halfs = 128B coalesced.
__global__ void k_thalf64(const float* __restrict__ in, __half* __restrict__ out,
                          int R, int C)
{
    __shared__ float s[64][33];
    const size_t zo = (size_t)blockIdx.z * R * C;
    const int c0 = blockIdx.x * 32;   // C block
    const int r0 = blockIdx.y * 64;   // R block
    const int tx = threadIdx.x & 31;
    const int w  = threadIdx.x >> 5;  // 8 warps

    #pragma unroll
    for (int rr = w; rr < 64; rr += 8)
        s[rr][tx] = in[zo + (size_t)(r0 + rr) * C + c0 + tx];
    __syncthreads();

    #pragma unroll
    for (int k = 0; k < 4; k++) {
        const int cc = w + 8 * k;
        __half2 v;
        v.x = __float2half_rn(s[2 * tx][cc]);
        v.y = __float2half_rn(s[2 * tx + 1][cc]);
        *(__half2*)(out + zo + (size_t)(c0 + cc) * R + r0 + 2 * tx) = v;
    }
}

// ---------------- attention (via r·eo) + per-head eo mixing ----------------
__global__ void attn_mix_kernel(const __half* __restrict__ q,
                                const __half* __restrict__ rb,
                                const __half* __restrict__ eo,
                                const float* __restrict__ bk,
                                __half* __restrict__ m,
                                const int* __restrict__ eidPtr)
{
    __shared__ __half2 eo_s[NE][DD / 2];   // 8 KB
    __shared__ __half2 r_s [NE][DD / 2];   // 8 KB
    const int n    = blockIdx.x;
    const int tid  = threadIdx.x;
    const int head = tid >> 5;
    const int lane = tid & 31;
    const int eid  = *eidPtr;

    #pragma unroll
    for (int t = 0; t < 2; t++) {
        const int j = tid + 256 * t;       // 0..511
        const int f = j >> 6;
        const int o = (j & 63) * 8;
        *(uint4*)&eo_s[f][o / 2] =
            *(const uint4*)(eo + (size_t)f * NTOK * DD + (size_t)n * DD + o);
        *(uint4*)&r_s[f][o / 2] =
            *(const uint4*)(rb + (size_t)f * NTOK * DD + (size_t)n * DD + o);
    }

    // c_h = q_h . bk_h
    const int hb = head * 64 + 2 * lane;
    const float2 qv = __half22float2(*(const __half2*)(q + (size_t)n * DD + hb));
    float ch = qv.x * bk[hb] + qv.y * bk[hb + 1];
    #pragma unroll
    for (int off = 16; off > 0; off >>= 1)
        ch += __shfl_xor_sync(0xffffffffu, ch, off);

    __syncthreads();

    float s[NE];
    #pragma unroll
    for (int f = 0; f < NE; f++) {
        float p = 0.f;
        #pragma unroll
        for (int c = 0; c < 8; c++) {
            const int d2 = lane + c * 32;
            const float2 rv = __half22float2(r_s[head][d2]);
            const float2 ev = __half22float2(eo_s[f][d2]);
            p += rv.x * ev.x + rv.y * ev.y;
        }
        #pragma unroll
        for (int off = 16; off > 0; off >>= 1)
            p += __shfl_xor_sync(0xffffffffu, p, off);
        s[f] = (p + ch) * 0.125f + ((f <= eid) ? 1.0f : 0.0f);
    }

    float mx = s[0];
    #pragma unroll
    for (int f = 1; f < NE; f++) mx = fmaxf(mx, s[f]);
    float sum = 0.f;
    #pragma unroll
    for (int f = 0; f < NE; f++) { s[f] = expf(s[f] - mx); sum += s[f]; }
    const float inv = 1.f / sum;
    #pragma unroll
    for (int f = 0; f < NE; f++) s[f] *= inv;

    __half* mh = m + (size_t)head * NTOK * DD + (size_t)n * DD;
    #pragma unroll
    for (int c = 0; c < 8; c++) {
        const int d2 = lane + c * 32;
        float ax = 0.f, ay = 0.f;
        #pragma unroll
        for (int f = 0; f < NE; f++) {
            const float2 v = __half22float2(eo_s[f][d2]);
            ax += s[f] * v.x; ay += s[f] * v.y;
        }
        __half2 o;
        o.x = __float2half_rn(ax); o.y = __float2half_rn(ay);
        *(__half2*)(mh + 2 * d2) = o;
    }
}

// -----------------------------------------------------------------------------
extern "C" void kernel_launch(void* const* d_in, const int* in_sizes, int n_in,
                              void* d_out, int out_size)
{
    const float* x  = (const float*)d_in[0];
    const float* W1 = (const float*)d_in[1];
    const float* b1 = (const float*)d_in[2];
    const float* W2 = (const float*)d_in[3];
    const float* b2 = (const float*)d_in[4];
    const float* Wq = (const float*)d_in[5];
    const float* bq = (const float*)d_in[6];
    const float* Wk = (const float*)d_in[7];
    const float* bk = (const float*)d_in[8];
    const float* Wv = (const float*)d_in[9];
    const float* bv = (const float*)d_in[10];
    const float* Wo = (const float*)d_in[11];
    const float* bo = (const float*)d_in[12];
    const int*  eid = (const int*)  d_in[13];

    __half *xh, *w1, *w2, *wq, *wkp, *wo, *wvp, *hid, *eo, *rb, *mb, *qb, *cx;
    float *zb;
    cudaGetSymbolAddress((void**)&xh,  g_x);
    cudaGetSymbolAddress((void**)&w1,  g_w1);
    cudaGetSymbolAddress((void**)&w2,  g_w2);
    cudaGetSymbolAddress((void**)&wq,  g_wq);
    cudaGetSymbolAddress((void**)&wkp, g_wkp);
    cudaGetSymbolAddress((void**)&wo,  g_wo);
    cudaGetSymbolAddress((void**)&wvp, g_wvp);
    cudaGetSymbolAddress((void**)&hid, g_hid);
    cudaGetSymbolAddress((void**)&eo,  g_eo);
    cudaGetSymbolAddress((void**)&rb,  g_r);
    cudaGetSymbolAddress((void**)&mb,  g_m);
    cudaGetSymbolAddress((void**)&qb,  g_q);
    cudaGetSymbolAddress((void**)&cx,  g_cx);
    cudaGetSymbolAddress((void**)&zb,  g_zerob);

    cudaFuncSetAttribute(mma_gemm<0, false>, cudaFuncAttributeMaxDynamicSharedMemorySize, SMEM_BYTES);
    cudaFuncSetAttribute(mma_gemm<1, false>, cudaFuncAttributeMaxDynamicSharedMemorySize, SMEM_BYTES);
    cudaFuncSetAttribute(mma_gemm<1, true>,  cudaFuncAttributeMaxDynamicSharedMemorySize, SMEM_BYTES);
    cudaFuncSetAttribute(mma_gemm<2, false>, cudaFuncAttributeMaxDynamicSharedMemorySize, SMEM_BYTES);

    // ---- conversions ----
    k_half<<<(NTOK * DD / 4 + 255) / 256, 256>>>(x, xh, NTOK * DD / 4);
    {   // W1 [E,512,2048] -> [E,2048,512]  (in R=512, C=2048)
        dim3 g(DFF / 32, DD / 64, NE);
        k_thalf64<<<g, 256>>>(W1, w1, DD, DFF);
    }
    {   // W2 [E,2048,512] -> [E,512,2048]  (in R=2048, C=512)
        dim3 g(DD / 32, DFF / 64, NE);
        k_thalf64<<<g, 256>>>(W2, w2, DFF, DD);
    }
    {   // Wq/Wo convert + Wv padded per-head
        dim3 g(NE * 128 * DD / 4 / 256, 3);
        k_half_w<<<g, 256>>>(Wq, Wo, Wv, wq, wo, wvp);
    }
    {   // Wk^T packed per head
        dim3 g(DD / 32, DD / 32), b(32, 8);
        k_wk_pack<<<g, b>>>(Wk, wkp);
    }

    // ---- FFN1: hidden[e] = relu(x @ W1[e] + b1[e]) ----
    mma_gemm<1, true><<<dim3(DFF / 128, NTOK / 128, NE), 256, SMEM_BYTES>>>(
        xh, w1, b1, nullptr, hid,
        DFF, DD, DD, 0, (size_t)DFF * DD, DFF, (size_t)NTOK * DFF, nullptr, 0);

    // ---- FFN2: eo[e] = hidden[e] @ W2[e] + b2[e] ----
    mma_gemm<1, false><<<dim3(DD / 128, NTOK / 128, NE), 256, SMEM_BYTES>>>(
        hid, w2, b2, nullptr, eo,
        DD, DFF, DFF, (size_t)NTOK * DFF, (size_t)DD * DFF, DD, (size_t)NTOK * DD, nullptr, 0);

    // ---- Q proj (expert_id slice only, fp16 out) ----
    mma_gemm<1, false><<<dim3(DD / 128, NTOK / 128, 1), 256, SMEM_BYTES>>>(
        eo, wq, bq, nullptr, qb,
        DD, DD, DD, 0, 0, 0, 0, eid, (size_t)NTOK * DD);

    // ---- r GEMM: r[h] = q[:, h*64:(h+1)*64] @ Wk_h  (M=4096, N=512, K=64) ----
    mma_gemm<1, false><<<dim3(DD / 128, NTOK / 128, NE), 256, SMEM_BYTES>>>(
        qb, wkp, zb, nullptr, rb,
        DD, 64, DD, 64 /*sA = column offset per head*/, (size_t)DD * 64, 0,
        (size_t)NTOK * DD, nullptr, 0);

    // ---- attention (r·eo scores) + mix ----
    attn_mix_kernel<<<NTOK, 256>>>(qb, rb, eo, bk, mb, eid);

    // ---- V proj on mixed vectors (per-head, N=64 valid of 128 tile) ----
    mma_gemm<2, false><<<dim3(1, NTOK / 128, NE), 256, SMEM_BYTES>>>(
        mb, wvp, bv, nullptr, cx,
        DD, DD, DD, (size_t)NTOK * DD, (size_t)128 * DD, 64, 64, nullptr, 0);

    // ---- out proj: d_out = ctx @ Wo^T + bo ----
    mma_gemm<0, false><<<dim3(DD / 128, NTOK / 128, 1), 256, SMEM_BYTES>>>(
        cx, wo, bo, (float*)d_out, nullptr,
        DD, DD, DD, 0, 0, 0, 0, nullptr, 0);
}